// round 9
// baseline (speedup 1.0000x reference)
#include <cuda_runtime.h>
#include <math.h>

#define B   2
#define NT  2048
#define DM  1024
#define H   16
#define HD  64
#define EPSF 1e-10f
#define NB_SINK 256

__device__ float g_Q[(size_t)B*H*NT*HD];
__device__ float g_K[(size_t)B*H*NT*HD];
__device__ float g_V[(size_t)B*H*NT*HD];
__device__ float g_E[(size_t)B*H*NT*NT];     // exp(scores), unnormalized
__device__ float g_P[(size_t)B*NT*NT];       // (mean_h attn + eps)^10, immutable
__device__ float g_ctx[(size_t)B*NT*DM];
__device__ float g_Z[(size_t)B*H*NT];
__device__ float g_T[(size_t)B*H*NT];
__device__ float g_Zi[(size_t)B*H*NT];
__device__ float g_u[B*NT];
__device__ float g_v[B*NT];
__device__ unsigned g_barcount = 0;
__device__ unsigned g_bargen = 0;

__device__ __forceinline__ unsigned cvt_tf32(float x){
    unsigned r; asm("cvt.rna.tf32.f32 %0, %1;" : "=r"(r) : "f"(x)); return r;
}
__device__ __forceinline__ void mma_tf32(float4 &c,
    unsigned a0, unsigned a1, unsigned a2, unsigned a3,
    unsigned b0, unsigned b1)
{
    asm("mma.sync.aligned.m16n8k8.row.col.f32.tf32.tf32.f32 "
        "{%0,%1,%2,%3},{%4,%5,%6,%7},{%8,%9},{%0,%1,%2,%3};"
        : "+f"(c.x), "+f"(c.y), "+f"(c.z), "+f"(c.w)
        : "r"(a0), "r"(a1), "r"(a2), "r"(a3), "r"(b0), "r"(b1));
}
__device__ __forceinline__ void cp16(unsigned d, const void* s){
    asm volatile("cp.async.cg.shared.global [%0], [%1], 16;\n" :: "r"(d), "l"(s));
}
__device__ __forceinline__ void cp_commit(){ asm volatile("cp.async.commit_group;\n"); }
__device__ __forceinline__ void cp_waitN(int rem){
    if (rem >= 2)      asm volatile("cp.async.wait_group 2;\n" ::: "memory");
    else if (rem == 1) asm volatile("cp.async.wait_group 1;\n" ::: "memory");
    else               asm volatile("cp.async.wait_group 0;\n" ::: "memory");
}

// ---------------------------------------------------------------------------
// C[m][e] = sum_k A[m][k]*W[e][k] + bias[e].  128x128 tile, BK=16, tf32 mma,
// 4-stage cp.async pipeline.  dyn smem 2*[4][128][20] f = 81920 B
// ---------------------------------------------------------------------------
__global__ __launch_bounds__(256, 2)
void gemm_nt_mma(const float* __restrict__ A, const float* __restrict__ W,
                 const float* __restrict__ bias, float* __restrict__ C,
                 int N, int K, int head_layout)
{
    extern __shared__ float smg[];
    float* Asm = smg;                // [4][128][20]
    float* Bsm = smg + 4*128*20;
    const unsigned sA = (unsigned)__cvta_generic_to_shared(Asm);
    const unsigned sB = (unsigned)__cvta_generic_to_shared(Bsm);

    const int tid = threadIdx.x, lane = tid & 31, warp = tid >> 5;
    const int gid = lane >> 2, tig = lane & 3;
    const int wm = warp & 1, wn = warp >> 1;
    const int bm0 = blockIdx.y * 128, bn0 = blockIdx.x * 128;
    const int lr = tid >> 1, lkq = (tid & 1) * 8;
    const float* Ag = A + (size_t)(bm0 + lr) * K + lkq;
    const float* Wg = W + (size_t)(bn0 + lr) * K + lkq;
    const int NCH = K / 16;

    float4 acc[4][4];
    #pragma unroll
    for (int i = 0; i < 4; i++)
        #pragma unroll
        for (int j = 0; j < 4; j++) acc[i][j] = make_float4(0.f,0.f,0.f,0.f);

    auto issue = [&](int cc){
        int st = cc & 3, k0 = cc * 16;
        unsigned da = sA + (unsigned)(((st*128 + lr)*20 + lkq)*4);
        cp16(da,      Ag + k0);
        cp16(da + 16, Ag + k0 + 4);
        unsigned db = sB + (unsigned)(((st*128 + lr)*20 + lkq)*4);
        cp16(db,      Wg + k0);
        cp16(db + 16, Wg + k0 + 4);
        cp_commit();
    };

    issue(0); issue(1); issue(2);

    for (int c = 0; c < NCH; c++) {
        cp_waitN(NCH - 1 - c);
        __syncthreads();
        if (c + 3 < NCH) issue(c + 3);
        const float* As_ = Asm + (c & 3)*128*20;
        const float* Bs_ = Bsm + (c & 3)*128*20;
        #pragma unroll
        for (int ks = 0; ks < 2; ks++) {
            const int kb = ks * 8;
            unsigned af[4][4];
            #pragma unroll
            for (int mt = 0; mt < 4; mt++) {
                int m = wm*64 + mt*16 + gid;
                af[mt][0] = cvt_tf32(As_[m*20     + kb + tig]);
                af[mt][1] = cvt_tf32(As_[(m+8)*20 + kb + tig]);
                af[mt][2] = cvt_tf32(As_[m*20     + kb + tig + 4]);
                af[mt][3] = cvt_tf32(As_[(m+8)*20 + kb + tig + 4]);
            }
            #pragma unroll
            for (int nt = 0; nt < 4; nt++) {
                int n = wn*32 + nt*8 + gid;
                unsigned b0 = cvt_tf32(Bs_[n*20 + kb + tig]);
                unsigned b1 = cvt_tf32(Bs_[n*20 + kb + tig + 4]);
                #pragma unroll
                for (int mt = 0; mt < 4; mt++)
                    mma_tf32(acc[mt][nt], af[mt][0],af[mt][1],af[mt][2],af[mt][3], b0, b1);
            }
        }
    }

    #pragma unroll
    for (int mt = 0; mt < 4; mt++) {
        int r0 = bm0 + wm*64 + mt*16 + gid;
        #pragma unroll
        for (int nt = 0; nt < 4; nt++) {
            int c0 = bn0 + wn*32 + nt*8 + tig*2;
            float bx = bias[c0], by = bias[c0+1];
            float2 lo = make_float2(acc[mt][nt].x + bx, acc[mt][nt].y + by);
            float2 hi = make_float2(acc[mt][nt].z + bx, acc[mt][nt].w + by);
            if (head_layout) {
                int bb = r0 >> 11, tok = r0 & 2047, hh = c0 >> 6, hd = c0 & 63;
                float* p = C + (((size_t)(bb*H + hh)*NT + tok)*HD) + hd;
                *(float2*)p = lo;
                *(float2*)(p + 8*HD) = hi;
            } else {
                float* p = C + (size_t)r0*N + c0;
                *(float2*)p = lo;
                *(float2*)(p + 8*(size_t)N) = hi;
            }
        }
    }
}

// ---------------------------------------------------------------------------
// Fused scores + exp + row Z/T/Zi.  Q pre-converted to tf32; 4-stage cp.async.
// dyn smem: Qs[128][68] u32 | Ks[4][128][20] f32 | pfi,pfj = 76800 B
// ---------------------------------------------------------------------------
__global__ __launch_bounds__(256, 2)
void scores_exp_mma(const float* __restrict__ pbs, const int* __restrict__ perm)
{
    extern __shared__ float sms[];
    unsigned* Qs = (unsigned*)sms;       // [128][68] tf32 bits
    float* Ksm = sms + 8704;             // [4][128][20] raw fp32
    float* pfi = sms + 8704 + 10240;
    float* pfj = pfi + 128;
    const unsigned sK = (unsigned)__cvta_generic_to_shared(Ksm);

    const int tid = threadIdx.x, lane = tid & 31, warp = tid >> 5;
    const int gid = lane >> 2, tig = lane & 3;
    const int wm = warp & 1, wn = warp >> 1;
    const int bh = blockIdx.y, b = bh >> 4, h = bh & 15;
    const int bi0 = blockIdx.x * 128;
    const float pb = fabsf(pbs[h]);

    const float* Qg = g_Q + ((size_t)bh*NT + bi0)*HD;
    const float* Kbase = g_K + (size_t)bh*NT*HD;
    const int lr = tid >> 1, lkq = (tid & 1) * 8;

    #pragma unroll
    for (int cq = 0; cq < 4; cq++) {
        int kk = lkq + cq*16;
        float4 q0 = *(const float4*)(Qg + (size_t)lr*HD + kk);
        float4 q1 = *(const float4*)(Qg + (size_t)lr*HD + kk + 4);
        uint4 t0, t1;
        t0.x=cvt_tf32(q0.x); t0.y=cvt_tf32(q0.y); t0.z=cvt_tf32(q0.z); t0.w=cvt_tf32(q0.w);
        t1.x=cvt_tf32(q1.x); t1.y=cvt_tf32(q1.y); t1.z=cvt_tf32(q1.z); t1.w=cvt_tf32(q1.w);
        *(uint4*)&Qs[lr*68 + kk]     = t0;
        *(uint4*)&Qs[lr*68 + kk + 4] = t1;
    }
    if (tid < 128) pfi[tid] = (float)perm[b*NT + bi0 + tid];

    float Zr[8] = {0,0,0,0,0,0,0,0};
    float Tr[8] = {0,0,0,0,0,0,0,0};

    auto issue = [&](int cc){
        int st = cc & 3, jt = cc >> 2, kc = (cc & 3) * 16;
        // NOTE: chunk c maps to j-tile c>>2, k-offset (c&3)*16; stage = c&3
        unsigned d = sK + (unsigned)(((st*128 + lr)*20 + lkq)*4);
        const float* s = Kbase + (size_t)(jt*128 + lr)*HD + (cc & 3)*16 + lkq;
        (void)kc;
        cp16(d, s); cp16(d + 16, s + 4);
        cp_commit();
    };

    issue(0); issue(1); issue(2);
    const int NCH = 64;

    for (int jt = 0; jt < 16; jt++) {
        const int j0 = jt * 128;
        float4 acc[4][4];
        #pragma unroll
        for (int i = 0; i < 4; i++)
            #pragma unroll
            for (int j = 0; j < 4; j++) acc[i][j] = make_float4(0.f,0.f,0.f,0.f);

        #pragma unroll
        for (int k4 = 0; k4 < 4; k4++) {
            const int c = jt*4 + k4;
            cp_waitN(NCH - 1 - c);
            __syncthreads();
            if (c + 3 < NCH) issue(c + 3);
            if (k4 == 0 && tid < 128) pfj[tid] = (float)perm[b*NT + j0 + tid];
            const float* Ks_ = Ksm + (c & 3)*128*20;
            const int kc = k4 * 16;
            #pragma unroll
            for (int ks = 0; ks < 2; ks++) {
                const int kb = ks * 8;
                unsigned af[4][4];
                #pragma unroll
                for (int mt = 0; mt < 4; mt++) {
                    int m = wm*64 + mt*16 + gid;
                    af[mt][0] = Qs[m*68     + kc + kb + tig];
                    af[mt][1] = Qs[(m+8)*68 + kc + kb + tig];
                    af[mt][2] = Qs[m*68     + kc + kb + tig + 4];
                    af[mt][3] = Qs[(m+8)*68 + kc + kb + tig + 4];
                }
                #pragma unroll
                for (int nt = 0; nt < 4; nt++) {
                    int n = wn*32 + nt*8 + gid;
                    unsigned b0 = cvt_tf32(Ks_[n*20 + kb + tig]);
                    unsigned b1 = cvt_tf32(Ks_[n*20 + kb + tig + 4]);
                    #pragma unroll
                    for (int mt = 0; mt < 4; mt++)
                        mma_tf32(acc[mt][nt], af[mt][0],af[mt][1],af[mt][2],af[mt][3], b0, b1);
                }
            }
        }

        #pragma unroll
        for (int mt = 0; mt < 4; mt++) {
            int rl = wm*64 + mt*16 + gid;
            float pa = pfi[rl], pc = pfi[rl+8];
            #pragma unroll
            for (int nt = 0; nt < 4; nt++) {
                int cl = wn*32 + nt*8 + tig*2;
                float d0 = pfj[cl], d1 = pfj[cl+1];
                float4 a = acc[mt][nt];
                float s00 = a.x*0.125f - fabsf(pa - d0)*pb;
                float s01 = a.y*0.125f - fabsf(pa - d1)*pb;
                float s10 = a.z*0.125f - fabsf(pc - d0)*pb;
                float s11 = a.w*0.125f - fabsf(pc - d1)*pb;
                float e00 = __expf(s00), e01 = __expf(s01);
                float e10 = __expf(s10), e11 = __expf(s11);
                Zr[mt*2]   += e00 + e01;  Tr[mt*2]   += s00*e00 + s01*e01;
                Zr[mt*2+1] += e10 + e11;  Tr[mt*2+1] += s10*e10 + s11*e11;
                size_t base = ((size_t)bh*NT + bi0 + rl)*NT + j0 + cl;
                *(float2*)(g_E + base)        = make_float2(e00, e01);
                *(float2*)(g_E + base + 8*NT) = make_float2(e10, e11);
            }
        }
    }

    float* red = (float*)Qs;
    const int pcol = wn*4 + tig;
    __syncthreads();
    #pragma unroll
    for (int mt = 0; mt < 4; mt++) {
        int r0 = wm*64 + mt*16 + gid;
        red[pcol*128 + r0]     = Zr[mt*2];
        red[pcol*128 + r0 + 8] = Zr[mt*2+1];
    }
    __syncthreads();
    if (tid < 128) {
        float s = 0.f;
        #pragma unroll
        for (int t = 0; t < 16; t++) s += red[t*128 + tid];
        g_Z[(size_t)bh*NT + bi0 + tid]  = s;
        g_Zi[(size_t)bh*NT + bi0 + tid] = 1.0f / s;
    }
    __syncthreads();
    #pragma unroll
    for (int mt = 0; mt < 4; mt++) {
        int r0 = wm*64 + mt*16 + gid;
        red[pcol*128 + r0]     = Tr[mt*2];
        red[pcol*128 + r0 + 8] = Tr[mt*2+1];
    }
    __syncthreads();
    if (tid < 128) {
        float s = 0.f;
        #pragma unroll
        for (int t = 0; t < 16; t++) s += red[t*128 + tid];
        g_T[(size_t)bh*NT + bi0 + tid] = s;
    }
}

// ---------------------------------------------------------------------------
// ctx = (E @ V) / Z.  4-stage cp.async; dyn smem 59904 B.
// ---------------------------------------------------------------------------
__global__ __launch_bounds__(256, 2)
void av_mma()
{
    extern __shared__ float sma[];
    float* Es_base = sma;                 // [4][128][20]
    float* Vs_base = sma + 4*128*20;      // [4][16][72]
    float* zin     = sma + 4*128*20 + 4*16*72;
    const unsigned sE = (unsigned)__cvta_generic_to_shared(Es_base);
    const unsigned sV = (unsigned)__cvta_generic_to_shared(Vs_base);

    const int tid = threadIdx.x, lane = tid & 31, warp = tid >> 5;
    const int gid = lane >> 2, tig = lane & 3;
    const int wm = warp >> 1, wn = warp & 1;
    const int bh = blockIdx.y, b = bh >> 4, h = bh & 15;
    const int bi0 = blockIdx.x * 128;

    const int lr = tid >> 1, lkq = (tid & 1) * 8;
    const float* Eg = g_E + ((size_t)bh*NT + bi0 + lr)*NT + lkq;
    const float* Vg = g_V + (size_t)bh*NT*HD;
    const int vr = tid >> 4, vcq = (tid & 15) * 4;

    if (tid < 128) zin[tid] = g_Zi[(size_t)bh*NT + bi0 + tid];

    float4 acc[2][4];
    #pragma unroll
    for (int i = 0; i < 2; i++)
        #pragma unroll
        for (int j = 0; j < 4; j++) acc[i][j] = make_float4(0.f,0.f,0.f,0.f);

    auto issue = [&](int cc){
        int st = cc & 3, k0 = cc * 16;
        unsigned dE = sE + (unsigned)(((st*128 + lr)*20 + lkq)*4);
        cp16(dE,      Eg + k0);
        cp16(dE + 16, Eg + k0 + 4);
        unsigned dV = sV + (unsigned)(((st*16 + vr)*72 + vcq)*4);
        cp16(dV, Vg + (size_t)(k0 + vr)*HD + vcq);
        cp_commit();
    };

    issue(0); issue(1); issue(2);
    const int NCH = NT / 16;   // 128

    for (int c = 0; c < NCH; c++) {
        cp_waitN(NCH - 1 - c);
        __syncthreads();
        if (c + 3 < NCH) issue(c + 3);
        const float* Es_ = Es_base + (c & 3)*128*20;
        const float* Vs_ = Vs_base + (c & 3)*16*72;
        #pragma unroll
        for (int ks = 0; ks < 2; ks++) {
            const int kb = ks * 8;
            unsigned af[2][4];
            #pragma unroll
            for (int mt = 0; mt < 2; mt++) {
                int m = wm*32 + mt*16 + gid;
                af[mt][0] = cvt_tf32(Es_[m*20     + kb + tig]);
                af[mt][1] = cvt_tf32(Es_[(m+8)*20 + kb + tig]);
                af[mt][2] = cvt_tf32(Es_[m*20     + kb + tig + 4]);
                af[mt][3] = cvt_tf32(Es_[(m+8)*20 + kb + tig + 4]);
            }
            #pragma unroll
            for (int nt = 0; nt < 4; nt++) {
                int n = wn*32 + nt*8 + gid;
                unsigned b0 = cvt_tf32(Vs_[(kb+tig)*72   + n]);
                unsigned b1 = cvt_tf32(Vs_[(kb+tig+4)*72 + n]);
                #pragma unroll
                for (int mt = 0; mt < 2; mt++)
                    mma_tf32(acc[mt][nt], af[mt][0],af[mt][1],af[mt][2],af[mt][3], b0, b1);
            }
        }
    }

    #pragma unroll
    for (int mt = 0; mt < 2; mt++) {
        int rl = wm*32 + mt*16 + gid;
        float z0 = zin[rl], z1 = zin[rl+8];
        #pragma unroll
        for (int nt = 0; nt < 4; nt++) {
            int cl = wn*32 + nt*8 + tig*2;
            float4 a = acc[mt][nt];
            size_t base = ((size_t)b*NT + bi0 + rl)*DM + h*HD + cl;
            *(float2*)(g_ctx + base)        = make_float2(a.x*z0, a.y*z0);
            *(float2*)(g_ctx + base + 8*DM) = make_float2(a.z*z1, a.w*z1);
        }
    }
}

// ---------------------------------------------------------------------------
// P raw: (mean_h attention + EPS)^10, float4-vectorized.
// ---------------------------------------------------------------------------
__global__ __launch_bounds__(256)
void build_P_kernel()
{
    size_t idx4 = ((size_t)blockIdx.x * 256 + threadIdx.x) * 4;
    size_t b = idx4 / ((size_t)NT*NT);
    size_t rem = idx4 - b * (size_t)NT*NT;
    int i = (int)(rem >> 11);
    float4 s = make_float4(0.f,0.f,0.f,0.f);
    #pragma unroll
    for (int h = 0; h < H; h++) {
        float4 e = *(const float4*)&g_E[(size_t)(b*H + h)*NT*NT + rem];
        float zi = g_Zi[(size_t)(b*H + h)*NT + i];
        s.x += e.x * zi; s.y += e.y * zi; s.z += e.z * zi; s.w += e.w * zi;
    }
    float4 o;
    o.x = expf(logf(s.x * (1.0f/16.0f) + EPSF) * 10.0f);
    o.y = expf(logf(s.y * (1.0f/16.0f) + EPSF) * 10.0f);
    o.z = expf(logf(s.z * (1.0f/16.0f) + EPSF) * 10.0f);
    o.w = expf(logf(s.w * (1.0f/16.0f) + EPSF) * 10.0f);
    *(float4*)&g_P[idx4] = o;
}

// ---------------------------------------------------------------------------
// Persistent Sinkhorn (diagonal scaling) + argmax + gather.
// ---------------------------------------------------------------------------
__device__ __forceinline__ void grid_sync(unsigned &gen)
{
    __syncthreads();
    if (threadIdx.x == 0) {
        gen++;
        __threadfence();
        unsigned old = atomicAdd(&g_barcount, 1);
        if (old == NB_SINK - 1) {
            atomicExch(&g_barcount, 0);
            atomicExch(&g_bargen, gen);
        } else {
            while (*(volatile unsigned*)&g_bargen < gen) __nanosleep(64);
        }
    }
    __syncthreads();
}

__global__ __launch_bounds__(256)
void sinkhorn_persist(const int* __restrict__ perm, float* __restrict__ outp)
{
    __shared__ float sv[NT];
    __shared__ float red[256];
    const int tid = threadIdx.x;
    const int bk = blockIdx.x;
    const int lane = tid & 31, w = tid >> 5;
    unsigned gen = *(volatile unsigned*)&g_bargen;

    const int row0 = bk * 16;
    const int bb = row0 >> 11;
    const int jbase = row0 & 2047;

    if (tid < 16) { __stcg(&g_u[row0 + tid], 1.0f); __stcg(&g_v[row0 + tid], 1.0f); }
    grid_sync(gen);

    for (int it = 0; it < 10; it++) {
        for (int j = tid; j < NT; j += 256) sv[j] = __ldcg(&g_v[bb*NT + j]);
        __syncthreads();
        #pragma unroll
        for (int rr = 0; rr < 2; rr++) {
            int r = row0 + w*2 + rr;
            const float* Pr = g_P + (size_t)r * NT;
            float s = 0.f;
            #pragma unroll 8
            for (int j = lane; j < NT; j += 32) s += Pr[j] * sv[j];
            #pragma unroll
            for (int o = 16; o > 0; o >>= 1) s += __shfl_xor_sync(0xffffffffu, s, o);
            if (lane == 0) {
                float u = __ldcg(&g_u[r]);
                __stcg(&g_u[r], u / (u * s + EPSF));
            }
        }
        grid_sync(gen);

        for (int i = tid; i < NT; i += 256) sv[i] = __ldcg(&g_u[bb*NT + i]);
        __syncthreads();
        {
            int c = tid & 15, rg = tid >> 4;
            const float* Pc = g_P + (size_t)bb*NT*NT + jbase + c;
            float s = 0.f;
            #pragma unroll 8
            for (int i = rg; i < NT; i += 16) s += Pc[(size_t)i*NT] * sv[i];
            red[tid] = s; __syncthreads();
            if (tid < 128) red[tid] += red[tid+128];
            __syncthreads();
            if (tid < 64)  red[tid] += red[tid+64];
            __syncthreads();
            if (tid < 32)  red[tid] += red[tid+32];
            __syncthreads();
            if (tid < 16) {
                float tot = red[tid] + red[tid+16];
                int jj = bb*NT + jbase + tid;
                float v = __ldcg(&g_v[jj]);
                __stcg(&g_v[jj], v / (v * tot + EPSF));
            }
            __syncthreads();
        }
        grid_sync(gen);
    }

    for (int j = tid; j < NT; j += 256) sv[j] = __ldcg(&g_v[bb*NT + j]);
    __syncthreads();
    #pragma unroll
    for (int rr = 0; rr < 2; rr++) {
        int r = row0 + w*2 + rr;
        const float* Pr = g_P + (size_t)r * NT;
        float best = -INFINITY; int bj = NT;
        for (int j = lane; j < NT; j += 32) {
            float val = Pr[j] * sv[j];
            if (val > best) { best = val; bj = j; }
        }
        #pragma unroll
        for (int o = 16; o > 0; o >>= 1) {
            float ob = __shfl_xor_sync(0xffffffffu, best, o);
            int   oj = __shfl_xor_sync(0xffffffffu, bj, o);
            if (ob > best || (ob == best && oj < bj)) { best = ob; bj = oj; }
        }
        if (lane == 0) outp[r] = (float)perm[bb*NT + bj];
    }
}

// ---------------------------------------------------------------------------
__global__ __launch_bounds__(256)
void cert_kernel(const float* __restrict__ cert, const float* __restrict__ ctemp,
                 float* __restrict__ out)
{
    const int idx = blockIdx.x * 256 + threadIdx.x;
    const int b = idx >> 11, i = idx & 2047;
    float s = 0.f;
    #pragma unroll
    for (int h = 0; h < H; h++) {
        size_t o = (size_t)(b*H + h)*NT + i;
        float Z = g_Z[o];
        s += logf(Z) - g_T[o] / Z;
    }
    float ent = s * (1.0f / 16.0f);
    float z = ctemp[0] * (logf(2048.0f) - ent);
    out[idx] = fmaxf(cert[idx], 1.0f / (1.0f + expf(-z)));
}

extern "C" void kernel_launch(void* const* d_in, const int* in_sizes, int n_in,
                              void* d_out, int out_size)
{
    const float* x     = (const float*)d_in[0];
    const float* cert  = (const float*)d_in[1];
    const int*   perm  = (const int*)  d_in[2];
    const float* Wq    = (const float*)d_in[3];
    const float* bq    = (const float*)d_in[4];
    const float* Wk    = (const float*)d_in[5];
    const float* bk    = (const float*)d_in[6];
    const float* Wv    = (const float*)d_in[7];
    const float* bvv   = (const float*)d_in[8];
    const float* Wo    = (const float*)d_in[9];
    const float* bo    = (const float*)d_in[10];
    const float* pbs   = (const float*)d_in[11];
    const float* ctemp = (const float*)d_in[12];
    float* out = (float*)d_out;

    float *pQ, *pK, *pV, *pCtx;
    cudaGetSymbolAddress((void**)&pQ,   g_Q);
    cudaGetSymbolAddress((void**)&pK,   g_K);
    cudaGetSymbolAddress((void**)&pV,   g_V);
    cudaGetSymbolAddress((void**)&pCtx, g_ctx);

    const int SMEM_G = 4*128*20*2*4;                       // 81920
    const int SMEM_S = (8704 + 4*128*20 + 256)*4;          // 76800
    const int SMEM_A = (4*128*20 + 4*16*72 + 128)*4;       // 59904
    cudaFuncSetAttribute(gemm_nt_mma,   cudaFuncAttributeMaxDynamicSharedMemorySize, SMEM_G);
    cudaFuncSetAttribute(scores_exp_mma,cudaFuncAttributeMaxDynamicSharedMemorySize, SMEM_S);
    cudaFuncSetAttribute(av_mma,        cudaFuncAttributeMaxDynamicSharedMemorySize, SMEM_A);

    const int M = B * NT;                  // 4096

    dim3 gProj(DM/128, M/128);             // (8, 32)
    gemm_nt_mma<<<gProj, 256, SMEM_G>>>(x, Wq, bq, pQ, DM, DM, 1);
    gemm_nt_mma<<<gProj, 256, SMEM_G>>>(x, Wk, bk, pK, DM, DM, 1);
    gemm_nt_mma<<<gProj, 256, SMEM_G>>>(x, Wv, bvv, pV, DM, DM, 1);

    dim3 gS(NT/128, B*H);                  // (16, 32)
    scores_exp_mma<<<gS, 256, SMEM_S>>>(pbs, perm);

    av_mma<<<gS, 256, SMEM_A>>>();

    gemm_nt_mma<<<gProj, 256, SMEM_G>>>(pCtx, Wo, bo, out, DM, DM, 0);

    cert_kernel<<<(B*NT)/256, 256>>>(cert, ctemp, out + (size_t)M*DM);

    build_P_kernel<<<8192, 256>>>();
    sinkhorn_persist<<<NB_SINK, 256>>>(perm, out + (size_t)M*DM + B*NT);
}

// round 10
// speedup vs baseline: 1.2616x; 1.2616x over previous
#include <cuda_runtime.h>
#include <cuda_fp16.h>
#include <math.h>

#define B   2
#define NT  2048
#define DM  1024
#define H   16
#define HD  64
#define EPSF 1e-10f
#define NB_SINK 256

__device__ __half g_Qh[(size_t)B*H*NT*HD];          // [bh][tok][hd]
__device__ __half g_Kh[(size_t)B*H*NT*HD];          // [bh][tok][hd]
__device__ __half g_Vh[(size_t)B*H*NT*HD];          // [bh][hd][tok]  (transposed)
__device__ __half g_Eh[(size_t)B*H*NT*NT];          // exp(scores), fp16
__device__ float g_P[(size_t)B*NT*NT];
__device__ float g_ctx[(size_t)B*NT*DM];
__device__ float g_Z[(size_t)B*H*NT];
__device__ float g_T[(size_t)B*H*NT];
__device__ float g_Zi[(size_t)B*H*NT];
__device__ float g_u[B*NT];
__device__ float g_v[B*NT];
__device__ unsigned g_barcount = 0;
__device__ unsigned g_bargen = 0;

__device__ __forceinline__ unsigned cvt_tf32(float x){
    unsigned r; asm("cvt.rna.tf32.f32 %0, %1;" : "=r"(r) : "f"(x)); return r;
}
__device__ __forceinline__ void mma_tf32(float4 &c,
    unsigned a0, unsigned a1, unsigned a2, unsigned a3,
    unsigned b0, unsigned b1)
{
    asm("mma.sync.aligned.m16n8k8.row.col.f32.tf32.tf32.f32 "
        "{%0,%1,%2,%3},{%4,%5,%6,%7},{%8,%9},{%0,%1,%2,%3};"
        : "+f"(c.x), "+f"(c.y), "+f"(c.z), "+f"(c.w)
        : "r"(a0), "r"(a1), "r"(a2), "r"(a3), "r"(b0), "r"(b1));
}
__device__ __forceinline__ void mma_f16(float4 &c,
    unsigned a0, unsigned a1, unsigned a2, unsigned a3,
    unsigned b0, unsigned b1)
{
    asm("mma.sync.aligned.m16n8k16.row.col.f32.f16.f16.f32 "
        "{%0,%1,%2,%3},{%4,%5,%6,%7},{%8,%9},{%0,%1,%2,%3};"
        : "+f"(c.x), "+f"(c.y), "+f"(c.z), "+f"(c.w)
        : "r"(a0), "r"(a1), "r"(a2), "r"(a3), "r"(b0), "r"(b1));
}
__device__ __forceinline__ void cp16(unsigned d, const void* s){
    asm volatile("cp.async.cg.shared.global [%0], [%1], 16;\n" :: "r"(d), "l"(s));
}
__device__ __forceinline__ void cp_commit(){ asm volatile("cp.async.commit_group;\n"); }
__device__ __forceinline__ void cp_wait1(){ asm volatile("cp.async.wait_group 1;\n" ::: "memory"); }
__device__ __forceinline__ void cp_wait0(){ asm volatile("cp.async.wait_group 0;\n" ::: "memory"); }

// ---------------------------------------------------------------------------
// C[m][e] = sum_k A[m][k]*W[e][k] + bias[e].  tf32 mma, 3-stage cp.async.
// omode: 0 = float row-major; 1 = half head-layout [bh][tok][hd] (Q,K);
//        2 = half transposed head-layout [bh][hd][tok] (V).
// ---------------------------------------------------------------------------
__global__ __launch_bounds__(256, 2)
void gemm_nt_mma(const float* __restrict__ A, const float* __restrict__ W,
                 const float* __restrict__ bias, void* __restrict__ C,
                 int N, int K, int omode)
{
    extern __shared__ float smg[];
    float* Asm = smg;                // [3][128][20]
    float* Bsm = smg + 3*128*20;
    const unsigned sA = (unsigned)__cvta_generic_to_shared(Asm);
    const unsigned sB = (unsigned)__cvta_generic_to_shared(Bsm);

    const int tid = threadIdx.x, lane = tid & 31, warp = tid >> 5;
    const int gid = lane >> 2, tig = lane & 3;
    const int wm = warp & 1, wn = warp >> 1;
    const int bm0 = blockIdx.y * 128, bn0 = blockIdx.x * 128;
    const int lr = tid >> 1, lkq = (tid & 1) * 8;
    const float* Ag = A + (size_t)(bm0 + lr) * K + lkq;
    const float* Wg = W + (size_t)(bn0 + lr) * K + lkq;
    const int NCH = K / 16;

    float4 acc[4][4];
    #pragma unroll
    for (int i = 0; i < 4; i++)
        #pragma unroll
        for (int j = 0; j < 4; j++) acc[i][j] = make_float4(0.f,0.f,0.f,0.f);

    auto issue = [&](int cc){
        int st = cc % 3, k0 = cc * 16;
        unsigned da = sA + (unsigned)(((st*128 + lr)*20 + lkq)*4);
        cp16(da,      Ag + k0);
        cp16(da + 16, Ag + k0 + 4);
        unsigned db = sB + (unsigned)(((st*128 + lr)*20 + lkq)*4);
        cp16(db,      Wg + k0);
        cp16(db + 16, Wg + k0 + 4);
        cp_commit();
    };

    issue(0); issue(1);

    for (int c = 0; c < NCH; c++) {
        if (c + 1 < NCH) cp_wait1(); else cp_wait0();
        __syncthreads();
        if (c + 2 < NCH) issue(c + 2);
        const float* As_ = Asm + (c % 3)*128*20;
        const float* Bs_ = Bsm + (c % 3)*128*20;
        #pragma unroll
        for (int ks = 0; ks < 2; ks++) {
            const int kb = ks * 8;
            unsigned af[4][4];
            #pragma unroll
            for (int mt = 0; mt < 4; mt++) {
                int m = wm*64 + mt*16 + gid;
                af[mt][0] = cvt_tf32(As_[m*20     + kb + tig]);
                af[mt][1] = cvt_tf32(As_[(m+8)*20 + kb + tig]);
                af[mt][2] = cvt_tf32(As_[m*20     + kb + tig + 4]);
                af[mt][3] = cvt_tf32(As_[(m+8)*20 + kb + tig + 4]);
            }
            #pragma unroll
            for (int nt = 0; nt < 4; nt++) {
                int n = wn*32 + nt*8 + gid;
                unsigned b0 = cvt_tf32(Bs_[n*20 + kb + tig]);
                unsigned b1 = cvt_tf32(Bs_[n*20 + kb + tig + 4]);
                #pragma unroll
                for (int mt = 0; mt < 4; mt++)
                    mma_tf32(acc[mt][nt], af[mt][0],af[mt][1],af[mt][2],af[mt][3], b0, b1);
            }
        }
    }

    #pragma unroll
    for (int mt = 0; mt < 4; mt++) {
        int r0 = bm0 + wm*64 + mt*16 + gid;
        #pragma unroll
        for (int nt = 0; nt < 4; nt++) {
            int c0 = bn0 + wn*32 + nt*8 + tig*2;
            float bx = bias[c0], by = bias[c0+1];
            float2 lo = make_float2(acc[mt][nt].x + bx, acc[mt][nt].y + by);
            float2 hi = make_float2(acc[mt][nt].z + bx, acc[mt][nt].w + by);
            if (omode == 0) {
                float* p = (float*)C + (size_t)r0*N + c0;
                *(float2*)p = lo;
                *(float2*)(p + 8*(size_t)N) = hi;
            } else {
                int bb = r0 >> 11, tok = r0 & 2047, hh = c0 >> 6, hd = c0 & 63;
                if (omode == 1) {
                    __half* p = (__half*)C + (((size_t)(bb*H + hh)*NT + tok)*HD) + hd;
                    *(__half2*)p          = __floats2half2_rn(lo.x, lo.y);
                    *(__half2*)(p + 8*HD) = __floats2half2_rn(hi.x, hi.y);
                } else {
                    __half* p = (__half*)C + ((size_t)(bb*H + hh)*HD + hd)*NT + tok;
                    p[0]      = __float2half_rn(lo.x);
                    p[NT]     = __float2half_rn(lo.y);
                    p[8]      = __float2half_rn(hi.x);
                    p[NT + 8] = __float2half_rn(hi.y);
                }
            }
        }
    }
}

// ---------------------------------------------------------------------------
// Fused scores + exp + row Z/T/Zi.  fp16 m16n8k16 mma; 3-stage cp.async on K.
// static smem: Qs[128][72]h, Ks[3][128][24]h, pfi/pfj  (~38 KB)
// ---------------------------------------------------------------------------
__global__ __launch_bounds__(256, 2)
void scores_exp_mma(const float* __restrict__ pbs, const int* __restrict__ perm)
{
    __shared__ __half Qs[128][72];
    __shared__ __half Ks[3][128][24];
    __shared__ float pfi[128], pfj[128];
    const unsigned sK = (unsigned)__cvta_generic_to_shared(&Ks[0][0][0]);

    const int tid = threadIdx.x, lane = tid & 31, warp = tid >> 5;
    const int gid = lane >> 2, tig = lane & 3;
    const int wm = warp & 1, wn = warp >> 1;
    const int bh = blockIdx.y, b = bh >> 4, h = bh & 15;
    const int bi0 = blockIdx.x * 128;
    const float pb = fabsf(pbs[h]);

    const __half* Qg = g_Qh + ((size_t)bh*NT + bi0)*HD;
    const __half* Kbase = g_Kh + (size_t)bh*NT*HD;
    const int lr = tid >> 1, lkq = (tid & 1) * 8;

    #pragma unroll
    for (int cq = 0; cq < 4; cq++) {
        int kk = lkq + cq*16;
        uint4 q = *(const uint4*)(Qg + (size_t)lr*HD + kk);
        *(uint4*)&Qs[lr][kk] = q;
    }
    if (tid < 128) pfi[tid] = (float)perm[b*NT + bi0 + tid];

    float Zr[8] = {0,0,0,0,0,0,0,0};
    float Tr[8] = {0,0,0,0,0,0,0,0};

    auto issue = [&](int cc){
        int st = cc % 3, jt = cc >> 2, kc = (cc & 3) * 16;
        unsigned d = sK + (unsigned)(((st*128 + lr)*24 + lkq)*2);
        cp16(d, Kbase + (size_t)(jt*128 + lr)*HD + kc + lkq);
        cp_commit();
    };

    issue(0); issue(1);
    const int NCH = 64;

    for (int jt = 0; jt < 16; jt++) {
        const int j0 = jt * 128;
        float4 acc[4][4];
        #pragma unroll
        for (int i = 0; i < 4; i++)
            #pragma unroll
            for (int j = 0; j < 4; j++) acc[i][j] = make_float4(0.f,0.f,0.f,0.f);

        #pragma unroll
        for (int k4 = 0; k4 < 4; k4++) {
            const int c = jt*4 + k4;
            if (c + 1 < NCH) cp_wait1(); else cp_wait0();
            __syncthreads();
            if (c + 2 < NCH) issue(c + 2);
            if (k4 == 0 && tid < 128) pfj[tid] = (float)perm[b*NT + j0 + tid];
            const __half* Ks_ = &Ks[c % 3][0][0];
            const int kc = k4 * 16;

            unsigned af[4][4];
            #pragma unroll
            for (int mt = 0; mt < 4; mt++) {
                int m = wm*64 + mt*16 + gid;
                af[mt][0] = *(const unsigned*)&Qs[m][kc + 2*tig];
                af[mt][1] = *(const unsigned*)&Qs[m+8][kc + 2*tig];
                af[mt][2] = *(const unsigned*)&Qs[m][kc + 2*tig + 8];
                af[mt][3] = *(const unsigned*)&Qs[m+8][kc + 2*tig + 8];
            }
            #pragma unroll
            for (int nt = 0; nt < 4; nt++) {
                int n = wn*32 + nt*8 + gid;
                unsigned b0 = *(const unsigned*)&Ks_[n*24 + 2*tig];
                unsigned b1 = *(const unsigned*)&Ks_[n*24 + 2*tig + 8];
                #pragma unroll
                for (int mt = 0; mt < 4; mt++)
                    mma_f16(acc[mt][nt], af[mt][0],af[mt][1],af[mt][2],af[mt][3], b0, b1);
            }
        }

        #pragma unroll
        for (int mt = 0; mt < 4; mt++) {
            int rl = wm*64 + mt*16 + gid;
            float pa = pfi[rl], pc = pfi[rl+8];
            #pragma unroll
            for (int nt = 0; nt < 4; nt++) {
                int cl = wn*32 + nt*8 + tig*2;
                float d0 = pfj[cl], d1 = pfj[cl+1];
                float4 a = acc[mt][nt];
                float s00 = a.x*0.125f - fabsf(pa - d0)*pb;
                float s01 = a.y*0.125f - fabsf(pa - d1)*pb;
                float s10 = a.z*0.125f - fabsf(pc - d0)*pb;
                float s11 = a.w*0.125f - fabsf(pc - d1)*pb;
                __half2 hA = __floats2half2_rn(__expf(s00), __expf(s01));
                __half2 hB = __floats2half2_rn(__expf(s10), __expf(s11));
                float2 fA = __half22float2(hA);
                float2 fB = __half22float2(hB);
                Zr[mt*2]   += fA.x + fA.y;  Tr[mt*2]   += s00*fA.x + s01*fA.y;
                Zr[mt*2+1] += fB.x + fB.y;  Tr[mt*2+1] += s10*fB.x + s11*fB.y;
                size_t base = ((size_t)bh*NT + bi0 + rl)*NT + j0 + cl;
                *(__half2*)(g_Eh + base)        = hA;
                *(__half2*)(g_Eh + base + 8*NT) = hB;
            }
        }
    }

    float* red = (float*)&Qs[0][0];   // 2048 floats scratch
    const int pcol = wn*4 + tig;
    __syncthreads();
    #pragma unroll
    for (int mt = 0; mt < 4; mt++) {
        int r0 = wm*64 + mt*16 + gid;
        red[pcol*128 + r0]     = Zr[mt*2];
        red[pcol*128 + r0 + 8] = Zr[mt*2+1];
    }
    __syncthreads();
    if (tid < 128) {
        float s = 0.f;
        #pragma unroll
        for (int t = 0; t < 16; t++) s += red[t*128 + tid];
        g_Z[(size_t)bh*NT + bi0 + tid]  = s;
        g_Zi[(size_t)bh*NT + bi0 + tid] = 1.0f / s;
    }
    __syncthreads();
    #pragma unroll
    for (int mt = 0; mt < 4; mt++) {
        int r0 = wm*64 + mt*16 + gid;
        red[pcol*128 + r0]     = Tr[mt*2];
        red[pcol*128 + r0 + 8] = Tr[mt*2+1];
    }
    __syncthreads();
    if (tid < 128) {
        float s = 0.f;
        #pragma unroll
        for (int t = 0; t < 16; t++) s += red[t*128 + tid];
        g_T[(size_t)bh*NT + bi0 + tid] = s;
    }
}

// ---------------------------------------------------------------------------
// ctx = (E @ V) / Z.  fp16 m16n8k16 mma; 3-stage cp.async.
// ---------------------------------------------------------------------------
__global__ __launch_bounds__(256, 2)
void av_mma()
{
    __shared__ __half Es[3][128][24];
    __shared__ __half Vs[3][64][24];
    __shared__ float zin[128];
    const unsigned sE = (unsigned)__cvta_generic_to_shared(&Es[0][0][0]);
    const unsigned sV = (unsigned)__cvta_generic_to_shared(&Vs[0][0][0]);

    const int tid = threadIdx.x, lane = tid & 31, warp = tid >> 5;
    const int gid = lane >> 2, tig = lane & 3;
    const int wm = warp >> 1, wn = warp & 1;
    const int bh = blockIdx.y, b = bh >> 4, h = bh & 15;
    const int bi0 = blockIdx.x * 128;

    const int lr = tid >> 1, lkq = (tid & 1) * 8;
    const __half* Eg = g_Eh + ((size_t)bh*NT + bi0 + lr)*NT + lkq;
    const __half* Vg = g_Vh + (size_t)bh*HD*NT;   // [hd][tok]
    const int vr = (tid & 127) >> 1;              // 0..63 for tid<128

    if (tid < 128) zin[tid] = g_Zi[(size_t)bh*NT + bi0 + tid];

    float4 acc[2][4];
    #pragma unroll
    for (int i = 0; i < 2; i++)
        #pragma unroll
        for (int j = 0; j < 4; j++) acc[i][j] = make_float4(0.f,0.f,0.f,0.f);

    auto issue = [&](int cc){
        int st = cc % 3, k0 = cc * 16;
        unsigned dE = sE + (unsigned)(((st*128 + lr)*24 + lkq)*2);
        cp16(dE, Eg + k0);
        if (tid < 128) {
            unsigned dV = sV + (unsigned)(((st*64 + vr)*24 + lkq)*2);
            cp16(dV, Vg + (size_t)vr*NT + k0 + lkq);
        }
        cp_commit();
    };

    issue(0); issue(1);
    const int NCH = NT / 16;   // 128

    for (int c = 0; c < NCH; c++) {
        if (c + 1 < NCH) cp_wait1(); else cp_wait0();
        __syncthreads();
        if (c + 2 < NCH) issue(c + 2);
        const __half* Es_ = &Es[c % 3][0][0];
        const __half* Vs_ = &Vs[c % 3][0][0];

        unsigned af[2][4];
        #pragma unroll
        for (int mt = 0; mt < 2; mt++) {
            int m = wm*32 + mt*16 + gid;
            af[mt][0] = *(const unsigned*)&Es_[m*24     + 2*tig];
            af[mt][1] = *(const unsigned*)&Es_[(m+8)*24 + 2*tig];
            af[mt][2] = *(const unsigned*)&Es_[m*24     + 2*tig + 8];
            af[mt][3] = *(const unsigned*)&Es_[(m+8)*24 + 2*tig + 8];
        }
        #pragma unroll
        for (int nt = 0; nt < 4; nt++) {
            int n = wn*32 + nt*8 + gid;
            unsigned b0 = *(const unsigned*)&Vs_[n*24 + 2*tig];
            unsigned b1 = *(const unsigned*)&Vs_[n*24 + 2*tig + 8];
            #pragma unroll
            for (int mt = 0; mt < 2; mt++)
                mma_f16(acc[mt][nt], af[mt][0],af[mt][1],af[mt][2],af[mt][3], b0, b1);
        }
    }

    #pragma unroll
    for (int mt = 0; mt < 2; mt++) {
        int rl = wm*32 + mt*16 + gid;
        float z0 = zin[rl], z1 = zin[rl+8];
        #pragma unroll
        for (int nt = 0; nt < 4; nt++) {
            int cl = wn*32 + nt*8 + tig*2;
            float4 a = acc[mt][nt];
            size_t base = ((size_t)b*NT + bi0 + rl)*DM + h*HD + cl;
            *(float2*)(g_ctx + base)        = make_float2(a.x*z0, a.y*z0);
            *(float2*)(g_ctx + base + 8*DM) = make_float2(a.z*z1, a.w*z1);
        }
    }
}

// ---------------------------------------------------------------------------
// P raw: (mean_h attention + EPS)^10, reading fp16 E 8-wide.
// ---------------------------------------------------------------------------
__global__ __launch_bounds__(256)
void build_P_kernel()
{
    size_t idx8 = ((size_t)blockIdx.x * 256 + threadIdx.x) * 8;
    size_t b = idx8 / ((size_t)NT*NT);
    size_t rem = idx8 - b * (size_t)NT*NT;
    int i = (int)(rem >> 11);
    float s[8] = {0,0,0,0,0,0,0,0};
    #pragma unroll
    for (int h = 0; h < H; h++) {
        uint4 raw = *(const uint4*)&g_Eh[(size_t)(b*H + h)*NT*NT + rem];
        float zi = g_Zi[(size_t)(b*H + h)*NT + i];
        float2 p0 = __half22float2(*(__half2*)&raw.x);
        float2 p1 = __half22float2(*(__half2*)&raw.y);
        float2 p2 = __half22float2(*(__half2*)&raw.z);
        float2 p3 = __half22float2(*(__half2*)&raw.w);
        s[0] += p0.x*zi; s[1] += p0.y*zi; s[2] += p1.x*zi; s[3] += p1.y*zi;
        s[4] += p2.x*zi; s[5] += p2.y*zi; s[6] += p3.x*zi; s[7] += p3.y*zi;
    }
    float o[8];
    #pragma unroll
    for (int k = 0; k < 8; k++)
        o[k] = expf(logf(s[k] * (1.0f/16.0f) + EPSF) * 10.0f);
    *(float4*)&g_P[idx8]     = make_float4(o[0],o[1],o[2],o[3]);
    *(float4*)&g_P[idx8 + 4] = make_float4(o[4],o[5],o[6],o[7]);
}

// ---------------------------------------------------------------------------
// Persistent Sinkhorn (diagonal scaling) + argmax + gather.
// ---------------------------------------------------------------------------
__device__ __forceinline__ void grid_sync(unsigned &gen)
{
    __syncthreads();
    if (threadIdx.x == 0) {
        gen++;
        __threadfence();
        unsigned old = atomicAdd(&g_barcount, 1);
        if (old == NB_SINK - 1) {
            atomicExch(&g_barcount, 0);
            atomicExch(&g_bargen, gen);
        } else {
            while (*(volatile unsigned*)&g_bargen < gen) __nanosleep(64);
        }
    }
    __syncthreads();
}

__global__ __launch_bounds__(256)
void sinkhorn_persist(const int* __restrict__ perm, float* __restrict__ outp)
{
    __shared__ float sv[NT];
    __shared__ float red[256];
    const int tid = threadIdx.x;
    const int bk = blockIdx.x;
    const int lane = tid & 31, w = tid >> 5;
    unsigned gen = *(volatile unsigned*)&g_bargen;

    const int row0 = bk * 16;
    const int bb = row0 >> 11;
    const int jbase = row0 & 2047;

    if (tid < 16) { __stcg(&g_u[row0 + tid], 1.0f); __stcg(&g_v[row0 + tid], 1.0f); }
    grid_sync(gen);

    for (int it = 0; it < 10; it++) {
        for (int j = tid; j < NT; j += 256) sv[j] = __ldcg(&g_v[bb*NT + j]);
        __syncthreads();
        #pragma unroll
        for (int rr = 0; rr < 2; rr++) {
            int r = row0 + w*2 + rr;
            const float* Pr = g_P + (size_t)r * NT;
            float s = 0.f;
            #pragma unroll 8
            for (int j = lane; j < NT; j += 32) s += Pr[j] * sv[j];
            #pragma unroll
            for (int o = 16; o > 0; o >>= 1) s += __shfl_xor_sync(0xffffffffu, s, o);
            if (lane == 0) {
                float u = __ldcg(&g_u[r]);
                __stcg(&g_u[r], u / (u * s + EPSF));
            }
        }
        grid_sync(gen);

        for (int i = tid; i < NT; i += 256) sv[i] = __ldcg(&g_u[bb*NT + i]);
        __syncthreads();
        {
            int c = tid & 15, rg = tid >> 4;
            const float* Pc = g_P + (size_t)bb*NT*NT + jbase + c;
            float s = 0.f;
            #pragma unroll 8
            for (int i = rg; i < NT; i += 16) s += Pc[(size_t)i*NT] * sv[i];
            red[tid] = s; __syncthreads();
            if (tid < 128) red[tid] += red[tid+128];
            __syncthreads();
            if (tid < 64)  red[tid] += red[tid+64];
            __syncthreads();
            if (tid < 32)  red[tid] += red[tid+32];
            __syncthreads();
            if (tid < 16) {
                float tot = red[tid] + red[tid+16];
                int jj = bb*NT + jbase + tid;
                float v = __ldcg(&g_v[jj]);
                __stcg(&g_v[jj], v / (v * tot + EPSF));
            }
            __syncthreads();
        }
        grid_sync(gen);
    }

    for (int j = tid; j < NT; j += 256) sv[j] = __ldcg(&g_v[bb*NT + j]);
    __syncthreads();
    #pragma unroll
    for (int rr = 0; rr < 2; rr++) {
        int r = row0 + w*2 + rr;
        const float* Pr = g_P + (size_t)r * NT;
        float best = -INFINITY; int bj = NT;
        for (int j = lane; j < NT; j += 32) {
            float val = Pr[j] * sv[j];
            if (val > best) { best = val; bj = j; }
        }
        #pragma unroll
        for (int o = 16; o > 0; o >>= 1) {
            float ob = __shfl_xor_sync(0xffffffffu, best, o);
            int   oj = __shfl_xor_sync(0xffffffffu, bj, o);
            if (ob > best || (ob == best && oj < bj)) { best = ob; bj = oj; }
        }
        if (lane == 0) outp[r] = (float)perm[bb*NT + bj];
    }
}

// ---------------------------------------------------------------------------
__global__ __launch_bounds__(256)
void cert_kernel(const float* __restrict__ cert, const float* __restrict__ ctemp,
                 float* __restrict__ out)
{
    const int idx = blockIdx.x * 256 + threadIdx.x;
    const int b = idx >> 11, i = idx & 2047;
    float s = 0.f;
    #pragma unroll
    for (int h = 0; h < H; h++) {
        size_t o = (size_t)(b*H + h)*NT + i;
        float Z = g_Z[o];
        s += logf(Z) - g_T[o] / Z;
    }
    float ent = s * (1.0f / 16.0f);
    float z = ctemp[0] * (logf(2048.0f) - ent);
    out[idx] = fmaxf(cert[idx], 1.0f / (1.0f + expf(-z)));
}

extern "C" void kernel_launch(void* const* d_in, const int* in_sizes, int n_in,
                              void* d_out, int out_size)
{
    const float* x     = (const float*)d_in[0];
    const float* cert  = (const float*)d_in[1];
    const int*   perm  = (const int*)  d_in[2];
    const float* Wq    = (const float*)d_in[3];
    const float* bq    = (const float*)d_in[4];
    const float* Wk    = (const float*)d_in[5];
    const float* bk    = (const float*)d_in[6];
    const float* Wv    = (const float*)d_in[7];
    const float* bvv   = (const float*)d_in[8];
    const float* Wo    = (const float*)d_in[9];
    const float* bo    = (const float*)d_in[10];
    const float* pbs   = (const float*)d_in[11];
    const float* ctemp = (const float*)d_in[12];
    float* out = (float*)d_out;

    void *pQ, *pK, *pV;
    float *pCtx;
    cudaGetSymbolAddress(&pQ, g_Qh);
    cudaGetSymbolAddress(&pK, g_Kh);
    cudaGetSymbolAddress(&pV, g_Vh);
    cudaGetSymbolAddress((void**)&pCtx, g_ctx);

    const int SMEM_G = 3*128*20*2*4;   // 61440
    cudaFuncSetAttribute(gemm_nt_mma, cudaFuncAttributeMaxDynamicSharedMemorySize, SMEM_G);

    const int M = B * NT;                  // 4096

    dim3 gProj(DM/128, M/128);             // (8, 32)
    gemm_nt_mma<<<gProj, 256, SMEM_G>>>(x, Wq, bq, pQ, DM, DM, 1);
    gemm_nt_mma<<<gProj, 256, SMEM_G>>>(x, Wk, bk, pK, DM, DM, 1);
    gemm_nt_mma<<<gProj, 256, SMEM_G>>>(x, Wv, bvv, pV, DM, DM, 2);

    dim3 gS(NT/128, B*H);                  // (16, 32)
    scores_exp_mma<<<gS, 256>>>(pbs, perm);

    av_mma<<<gS, 256>>>();

    gemm_nt_mma<<<gProj, 256, SMEM_G>>>(pCtx, Wo, bo, out, DM, DM, 0);

    cert_kernel<<<(B*NT)/256, 256>>>(cert, ctemp, out + (size_t)M*DM);

    build_P_kernel<<<4096, 256>>>();
    sinkhorn_persist<<<NB_SINK, 256>>>(perm, out + (size_t)M*DM + B*NT);
}

// round 11
// speedup vs baseline: 1.4798x; 1.1729x over previous
#include <cuda_runtime.h>
#include <cuda_fp16.h>
#include <math.h>

#define B   2
#define NT  2048
#define DM  1024
#define H   16
#define HD  64
#define EPSF 1e-10f
#define NB_SINK 256

__device__ __half g_xh[(size_t)B*NT*DM];            // x in fp16
__device__ __half g_Wqkvh[(size_t)3*DM*DM];         // [Wq;Wk;Wv] fp16, row-major [3072][1024]
__device__ __half g_Woh[(size_t)DM*DM];
__device__ float  g_bqkv[3*DM];
__device__ __half g_Qh[(size_t)B*H*NT*HD];          // [bh][tok][hd]
__device__ __half g_Kh[(size_t)B*H*NT*HD];          // [bh][tok][hd]
__device__ __half g_Vh[(size_t)B*H*NT*HD];          // [bh][hd][tok]  (transposed)
__device__ __half g_Eh[(size_t)B*H*NT*NT];          // exp(scores), fp16
__device__ __half g_ctxh[(size_t)B*NT*DM];
__device__ float g_P[(size_t)B*NT*NT];
__device__ float g_Z[(size_t)B*H*NT];
__device__ float g_T[(size_t)B*H*NT];
__device__ float g_Zi[(size_t)B*H*NT];
__device__ float g_u[B*NT];
__device__ float g_v[B*NT];
__device__ unsigned g_barcount = 0;
__device__ unsigned g_bargen = 0;

__device__ __forceinline__ void mma_f16(float4 &c,
    unsigned a0, unsigned a1, unsigned a2, unsigned a3,
    unsigned b0, unsigned b1)
{
    asm("mma.sync.aligned.m16n8k16.row.col.f32.f16.f16.f32 "
        "{%0,%1,%2,%3},{%4,%5,%6,%7},{%8,%9},{%0,%1,%2,%3};"
        : "+f"(c.x), "+f"(c.y), "+f"(c.z), "+f"(c.w)
        : "r"(a0), "r"(a1), "r"(a2), "r"(a3), "r"(b0), "r"(b1));
}
__device__ __forceinline__ void cp16(unsigned d, const void* s){
    asm volatile("cp.async.cg.shared.global [%0], [%1], 16;\n" :: "r"(d), "l"(s));
}
__device__ __forceinline__ void cp_commit(){ asm volatile("cp.async.commit_group;\n"); }
__device__ __forceinline__ void cp_wait1(){ asm volatile("cp.async.wait_group 1;\n" ::: "memory"); }
__device__ __forceinline__ void cp_wait0(){ asm volatile("cp.async.wait_group 0;\n" ::: "memory"); }

// ---------------------------------------------------------------------------
// float -> half elementwise (vectorized x4)
// ---------------------------------------------------------------------------
__global__ __launch_bounds__(256)
void cvt_f2h(const float* __restrict__ src, __half* __restrict__ dst, int n4)
{
    int i = blockIdx.x * 256 + threadIdx.x;
    if (i < n4) {
        float4 v = ((const float4*)src)[i];
        ((__half2*)dst)[2*i]   = __floats2half2_rn(v.x, v.y);
        ((__half2*)dst)[2*i+1] = __floats2half2_rn(v.z, v.w);
    }
}

__global__ __launch_bounds__(256)
void concat_bias(const float* __restrict__ bq, const float* __restrict__ bk,
                 const float* __restrict__ bv)
{
    int i = blockIdx.x * 256 + threadIdx.x;   // 0..3071
    float v = (i < 1024) ? bq[i] : (i < 2048 ? bk[i-1024] : bv[i-2048]);
    g_bqkv[i] = v;
}

// ---------------------------------------------------------------------------
// fp16 GEMM: C[m][e] = sum_k A[m][k]*W[e][k] + bias[e].  128x128 tile, BK=32,
// m16n8k16 mma, 3-stage cp.async.  dyn smem 2*[3][128][40] halves = 61440 B.
// omode 0: float row-major out (bias = per-call pointer)
// omode 3: fused QKV out -> g_Qh/g_Kh head layout, g_Vh transposed (bias g_bqkv)
// ---------------------------------------------------------------------------
__global__ __launch_bounds__(256, 2)
void gemm_h(const __half* __restrict__ A, const __half* __restrict__ W,
            const float* __restrict__ bias, float* __restrict__ C,
            int N, int K, int omode)
{
    extern __shared__ __half smh[];
    __half* Asm = smh;                 // [3][128][40]
    __half* Bsm = smh + 3*128*40;
    const unsigned sA = (unsigned)__cvta_generic_to_shared(Asm);
    const unsigned sB = (unsigned)__cvta_generic_to_shared(Bsm);

    const int tid = threadIdx.x, lane = tid & 31, warp = tid >> 5;
    const int gid = lane >> 2, tig = lane & 3;
    const int wm = warp & 1, wn = warp >> 1;
    const int bm0 = blockIdx.y * 128, bn0 = blockIdx.x * 128;
    const int lr = tid >> 1, lkq = (tid & 1) * 16;
    const __half* Ag = A + (size_t)(bm0 + lr) * K + lkq;
    const __half* Wg = W + (size_t)(bn0 + lr) * K + lkq;
    const int NCH = K / 32;

    float4 acc[4][4];
    #pragma unroll
    for (int i = 0; i < 4; i++)
        #pragma unroll
        for (int j = 0; j < 4; j++) acc[i][j] = make_float4(0.f,0.f,0.f,0.f);

    auto issue = [&](int cc){
        int st = cc % 3, k0 = cc * 32;
        unsigned da = sA + (unsigned)(((st*128 + lr)*40 + lkq)*2);
        cp16(da,      Ag + k0);
        cp16(da + 16, Ag + k0 + 8);
        unsigned db = sB + (unsigned)(((st*128 + lr)*40 + lkq)*2);
        cp16(db,      Wg + k0);
        cp16(db + 16, Wg + k0 + 8);
        cp_commit();
    };

    issue(0); issue(1);

    for (int c = 0; c < NCH; c++) {
        if (c + 1 < NCH) cp_wait1(); else cp_wait0();
        __syncthreads();
        if (c + 2 < NCH) issue(c + 2);
        const __half* As_ = Asm + (c % 3)*128*40;
        const __half* Bs_ = Bsm + (c % 3)*128*40;
        #pragma unroll
        for (int ks = 0; ks < 2; ks++) {
            const int kb = ks * 16;
            unsigned af[4][4];
            #pragma unroll
            for (int mt = 0; mt < 4; mt++) {
                int m = wm*64 + mt*16 + gid;
                af[mt][0] = *(const unsigned*)&As_[m*40     + kb + 2*tig];
                af[mt][1] = *(const unsigned*)&As_[(m+8)*40 + kb + 2*tig];
                af[mt][2] = *(const unsigned*)&As_[m*40     + kb + 2*tig + 8];
                af[mt][3] = *(const unsigned*)&As_[(m+8)*40 + kb + 2*tig + 8];
            }
            #pragma unroll
            for (int nt = 0; nt < 4; nt++) {
                int n = wn*32 + nt*8 + gid;
                unsigned b0 = *(const unsigned*)&Bs_[n*40 + kb + 2*tig];
                unsigned b1 = *(const unsigned*)&Bs_[n*40 + kb + 2*tig + 8];
                #pragma unroll
                for (int mt = 0; mt < 4; mt++)
                    mma_f16(acc[mt][nt], af[mt][0],af[mt][1],af[mt][2],af[mt][3], b0, b1);
            }
        }
    }

    #pragma unroll
    for (int mt = 0; mt < 4; mt++) {
        int r0 = bm0 + wm*64 + mt*16 + gid;
        #pragma unroll
        for (int nt = 0; nt < 4; nt++) {
            int c0 = bn0 + wn*32 + nt*8 + tig*2;
            float bx, by;
            if (omode == 3) { bx = g_bqkv[c0]; by = g_bqkv[c0+1]; }
            else            { bx = bias[c0];   by = bias[c0+1];   }
            float2 lo = make_float2(acc[mt][nt].x + bx, acc[mt][nt].y + by);
            float2 hi = make_float2(acc[mt][nt].z + bx, acc[mt][nt].w + by);
            if (omode == 0) {
                float* p = C + (size_t)r0*N + c0;
                *(float2*)p = lo;
                *(float2*)(p + 8*(size_t)N) = hi;
            } else {
                int which = c0 >> 10;
                int e = c0 & 1023;
                int bb = r0 >> 11, tok = r0 & 2047, hh = e >> 6, hd = e & 63;
                size_t bh = (size_t)(bb*H + hh);
                if (which == 0) {
                    __half* p = g_Qh + (bh*NT + tok)*HD + hd;
                    *(__half2*)p          = __floats2half2_rn(lo.x, lo.y);
                    *(__half2*)(p + 8*HD) = __floats2half2_rn(hi.x, hi.y);
                } else if (which == 1) {
                    __half* p = g_Kh + (bh*NT + tok)*HD + hd;
                    *(__half2*)p          = __floats2half2_rn(lo.x, lo.y);
                    *(__half2*)(p + 8*HD) = __floats2half2_rn(hi.x, hi.y);
                } else {
                    __half* p = g_Vh + (bh*HD + hd)*NT + tok;
                    p[0]      = __float2half_rn(lo.x);
                    p[NT]     = __float2half_rn(lo.y);
                    p[8]      = __float2half_rn(hi.x);
                    p[NT + 8] = __float2half_rn(hi.y);
                }
            }
        }
    }
}

// ---------------------------------------------------------------------------
// Fused scores + exp + row Z/T/Zi.  fp16 m16n8k16 mma; 3-stage cp.async on K.
// ---------------------------------------------------------------------------
__global__ __launch_bounds__(256, 2)
void scores_exp_mma(const float* __restrict__ pbs, const int* __restrict__ perm)
{
    __shared__ __half Qs[128][72];
    __shared__ __half Ks[3][128][24];
    __shared__ float pfi[128], pfj[128];
    const unsigned sK = (unsigned)__cvta_generic_to_shared(&Ks[0][0][0]);

    const int tid = threadIdx.x, lane = tid & 31, warp = tid >> 5;
    const int gid = lane >> 2, tig = lane & 3;
    const int wm = warp & 1, wn = warp >> 1;
    const int bh = blockIdx.y, b = bh >> 4, h = bh & 15;
    const int bi0 = blockIdx.x * 128;
    const float pb = fabsf(pbs[h]);

    const __half* Qg = g_Qh + ((size_t)bh*NT + bi0)*HD;
    const __half* Kbase = g_Kh + (size_t)bh*NT*HD;
    const int lr = tid >> 1, lkq = (tid & 1) * 8;

    #pragma unroll
    for (int cq = 0; cq < 4; cq++) {
        int kk = lkq + cq*16;
        uint4 q = *(const uint4*)(Qg + (size_t)lr*HD + kk);
        *(uint4*)&Qs[lr][kk] = q;
    }
    if (tid < 128) pfi[tid] = (float)perm[b*NT + bi0 + tid];

    float Zr[8] = {0,0,0,0,0,0,0,0};
    float Tr[8] = {0,0,0,0,0,0,0,0};

    auto issue = [&](int cc){
        int st = cc % 3, jt = cc >> 2, kc = (cc & 3) * 16;
        unsigned d = sK + (unsigned)(((st*128 + lr)*24 + lkq)*2);
        cp16(d, Kbase + (size_t)(jt*128 + lr)*HD + kc + lkq);
        cp_commit();
    };

    issue(0); issue(1);
    const int NCH = 64;

    for (int jt = 0; jt < 16; jt++) {
        const int j0 = jt * 128;
        float4 acc[4][4];
        #pragma unroll
        for (int i = 0; i < 4; i++)
            #pragma unroll
            for (int j = 0; j < 4; j++) acc[i][j] = make_float4(0.f,0.f,0.f,0.f);

        #pragma unroll
        for (int k4 = 0; k4 < 4; k4++) {
            const int c = jt*4 + k4;
            if (c + 1 < NCH) cp_wait1(); else cp_wait0();
            __syncthreads();
            if (c + 2 < NCH) issue(c + 2);
            if (k4 == 0 && tid < 128) pfj[tid] = (float)perm[b*NT + j0 + tid];
            const __half* Ks_ = &Ks[c % 3][0][0];
            const int kc = k4 * 16;

            unsigned af[4][4];
            #pragma unroll
            for (int mt = 0; mt < 4; mt++) {
                int m = wm*64 + mt*16 + gid;
                af[mt][0] = *(const unsigned*)&Qs[m][kc + 2*tig];
                af[mt][1] = *(const unsigned*)&Qs[m+8][kc + 2*tig];
                af[mt][2] = *(const unsigned*)&Qs[m][kc + 2*tig + 8];
                af[mt][3] = *(const unsigned*)&Qs[m+8][kc + 2*tig + 8];
            }
            #pragma unroll
            for (int nt = 0; nt < 4; nt++) {
                int n = wn*32 + nt*8 + gid;
                unsigned b0 = *(const unsigned*)&Ks_[n*24 + 2*tig];
                unsigned b1 = *(const unsigned*)&Ks_[n*24 + 2*tig + 8];
                #pragma unroll
                for (int mt = 0; mt < 4; mt++)
                    mma_f16(acc[mt][nt], af[mt][0],af[mt][1],af[mt][2],af[mt][3], b0, b1);
            }
        }

        #pragma unroll
        for (int mt = 0; mt < 4; mt++) {
            int rl = wm*64 + mt*16 + gid;
            float pa = pfi[rl], pc = pfi[rl+8];
            #pragma unroll
            for (int nt = 0; nt < 4; nt++) {
                int cl = wn*32 + nt*8 + tig*2;
                float d0 = pfj[cl], d1 = pfj[cl+1];
                float4 a = acc[mt][nt];
                float s00 = a.x*0.125f - fabsf(pa - d0)*pb;
                float s01 = a.y*0.125f - fabsf(pa - d1)*pb;
                float s10 = a.z*0.125f - fabsf(pc - d0)*pb;
                float s11 = a.w*0.125f - fabsf(pc - d1)*pb;
                __half2 hA = __floats2half2_rn(__expf(s00), __expf(s01));
                __half2 hB = __floats2half2_rn(__expf(s10), __expf(s11));
                float2 fA = __half22float2(hA);
                float2 fB = __half22float2(hB);
                Zr[mt*2]   += fA.x + fA.y;  Tr[mt*2]   += s00*fA.x + s01*fA.y;
                Zr[mt*2+1] += fB.x + fB.y;  Tr[mt*2+1] += s10*fB.x + s11*fB.y;
                size_t base = ((size_t)bh*NT + bi0 + rl)*NT + j0 + cl;
                *(__half2*)(g_Eh + base)        = hA;
                *(__half2*)(g_Eh + base + 8*NT) = hB;
            }
        }
    }

    float* red = (float*)&Qs[0][0];
    const int pcol = wn*4 + tig;
    __syncthreads();
    #pragma unroll
    for (int mt = 0; mt < 4; mt++) {
        int r0 = wm*64 + mt*16 + gid;
        red[pcol*128 + r0]     = Zr[mt*2];
        red[pcol*128 + r0 + 8] = Zr[mt*2+1];
    }
    __syncthreads();
    if (tid < 128) {
        float s = 0.f;
        #pragma unroll
        for (int t = 0; t < 16; t++) s += red[t*128 + tid];
        g_Z[(size_t)bh*NT + bi0 + tid]  = s;
        g_Zi[(size_t)bh*NT + bi0 + tid] = 1.0f / s;
    }
    __syncthreads();
    #pragma unroll
    for (int mt = 0; mt < 4; mt++) {
        int r0 = wm*64 + mt*16 + gid;
        red[pcol*128 + r0]     = Tr[mt*2];
        red[pcol*128 + r0 + 8] = Tr[mt*2+1];
    }
    __syncthreads();
    if (tid < 128) {
        float s = 0.f;
        #pragma unroll
        for (int t = 0; t < 16; t++) s += red[t*128 + tid];
        g_T[(size_t)bh*NT + bi0 + tid] = s;
    }
}

// ---------------------------------------------------------------------------
// ctx(half) = (E @ V) / Z.  fp16 m16n8k16 mma; 3-stage cp.async.
// ---------------------------------------------------------------------------
__global__ __launch_bounds__(256, 2)
void av_mma()
{
    __shared__ __half Es[3][128][24];
    __shared__ __half Vs[3][64][24];
    __shared__ float zin[128];
    const unsigned sE = (unsigned)__cvta_generic_to_shared(&Es[0][0][0]);
    const unsigned sV = (unsigned)__cvta_generic_to_shared(&Vs[0][0][0]);

    const int tid = threadIdx.x, lane = tid & 31, warp = tid >> 5;
    const int gid = lane >> 2, tig = lane & 3;
    const int wm = warp >> 1, wn = warp & 1;
    const int bh = blockIdx.y, b = bh >> 4, h = bh & 15;
    const int bi0 = blockIdx.x * 128;

    const int lr = tid >> 1, lkq = (tid & 1) * 8;
    const __half* Eg = g_Eh + ((size_t)bh*NT + bi0 + lr)*NT + lkq;
    const __half* Vg = g_Vh + (size_t)bh*HD*NT;   // [hd][tok]
    const int vr = (tid & 127) >> 1;

    if (tid < 128) zin[tid] = g_Zi[(size_t)bh*NT + bi0 + tid];

    float4 acc[2][4];
    #pragma unroll
    for (int i = 0; i < 2; i++)
        #pragma unroll
        for (int j = 0; j < 4; j++) acc[i][j] = make_float4(0.f,0.f,0.f,0.f);

    auto issue = [&](int cc){
        int st = cc % 3, k0 = cc * 16;
        unsigned dE = sE + (unsigned)(((st*128 + lr)*24 + lkq)*2);
        cp16(dE, Eg + k0);
        if (tid < 128) {
            unsigned dV = sV + (unsigned)(((st*64 + vr)*24 + lkq)*2);
            cp16(dV, Vg + (size_t)vr*NT + k0 + lkq);
        }
        cp_commit();
    };

    issue(0); issue(1);
    const int NCH = NT / 16;

    for (int c = 0; c < NCH; c++) {
        if (c + 1 < NCH) cp_wait1(); else cp_wait0();
        __syncthreads();
        if (c + 2 < NCH) issue(c + 2);
        const __half* Es_ = &Es[c % 3][0][0];
        const __half* Vs_ = &Vs[c % 3][0][0];

        unsigned af[2][4];
        #pragma unroll
        for (int mt = 0; mt < 2; mt++) {
            int m = wm*32 + mt*16 + gid;
            af[mt][0] = *(const unsigned*)&Es_[m*24     + 2*tig];
            af[mt][1] = *(const unsigned*)&Es_[(m+8)*24 + 2*tig];
            af[mt][2] = *(const unsigned*)&Es_[m*24     + 2*tig + 8];
            af[mt][3] = *(const unsigned*)&Es_[(m+8)*24 + 2*tig + 8];
        }
        #pragma unroll
        for (int nt = 0; nt < 4; nt++) {
            int n = wn*32 + nt*8 + gid;
            unsigned b0 = *(const unsigned*)&Vs_[n*24 + 2*tig];
            unsigned b1 = *(const unsigned*)&Vs_[n*24 + 2*tig + 8];
            #pragma unroll
            for (int mt = 0; mt < 2; mt++)
                mma_f16(acc[mt][nt], af[mt][0],af[mt][1],af[mt][2],af[mt][3], b0, b1);
        }
    }

    #pragma unroll
    for (int mt = 0; mt < 2; mt++) {
        int rl = wm*32 + mt*16 + gid;
        float z0 = zin[rl], z1 = zin[rl+8];
        #pragma unroll
        for (int nt = 0; nt < 4; nt++) {
            int cl = wn*32 + nt*8 + tig*2;
            float4 a = acc[mt][nt];
            size_t base = ((size_t)b*NT + bi0 + rl)*DM + h*HD + cl;
            *(__half2*)(g_ctxh + base)        = __floats2half2_rn(a.x*z0, a.y*z0);
            *(__half2*)(g_ctxh + base + 8*DM) = __floats2half2_rn(a.z*z1, a.w*z1);
        }
    }
}

// ---------------------------------------------------------------------------
// P raw: (mean_h attention + EPS)^10, reading fp16 E 8-wide.
// ---------------------------------------------------------------------------
__global__ __launch_bounds__(256)
void build_P_kernel()
{
    size_t idx8 = ((size_t)blockIdx.x * 256 + threadIdx.x) * 8;
    size_t b = idx8 / ((size_t)NT*NT);
    size_t rem = idx8 - b * (size_t)NT*NT;
    int i = (int)(rem >> 11);
    float s[8] = {0,0,0,0,0,0,0,0};
    #pragma unroll
    for (int h = 0; h < H; h++) {
        uint4 raw = *(const uint4*)&g_Eh[(size_t)(b*H + h)*NT*NT + rem];
        float zi = g_Zi[(size_t)(b*H + h)*NT + i];
        float2 p0 = __half22float2(*(__half2*)&raw.x);
        float2 p1 = __half22float2(*(__half2*)&raw.y);
        float2 p2 = __half22float2(*(__half2*)&raw.z);
        float2 p3 = __half22float2(*(__half2*)&raw.w);
        s[0] += p0.x*zi; s[1] += p0.y*zi; s[2] += p1.x*zi; s[3] += p1.y*zi;
        s[4] += p2.x*zi; s[5] += p2.y*zi; s[6] += p3.x*zi; s[7] += p3.y*zi;
    }
    float o[8];
    #pragma unroll
    for (int k = 0; k < 8; k++)
        o[k] = expf(logf(s[k] * (1.0f/16.0f) + EPSF) * 10.0f);
    *(float4*)&g_P[idx8]     = make_float4(o[0],o[1],o[2],o[3]);
    *(float4*)&g_P[idx8 + 4] = make_float4(o[4],o[5],o[6],o[7]);
}

// ---------------------------------------------------------------------------
// Persistent Sinkhorn (diagonal scaling) + argmax + gather.
// ---------------------------------------------------------------------------
__device__ __forceinline__ void grid_sync(unsigned &gen)
{
    __syncthreads();
    if (threadIdx.x == 0) {
        gen++;
        __threadfence();
        unsigned old = atomicAdd(&g_barcount, 1);
        if (old == NB_SINK - 1) {
            atomicExch(&g_barcount, 0);
            atomicExch(&g_bargen, gen);
        } else {
            while (*(volatile unsigned*)&g_bargen < gen) __nanosleep(64);
        }
    }
    __syncthreads();
}

__global__ __launch_bounds__(256)
void sinkhorn_persist(const int* __restrict__ perm, float* __restrict__ outp)
{
    __shared__ float sv[NT];
    __shared__ float red[256];
    const int tid = threadIdx.x;
    const int bk = blockIdx.x;
    const int lane = tid & 31, w = tid >> 5;
    unsigned gen = *(volatile unsigned*)&g_bargen;

    const int row0 = bk * 16;
    const int bb = row0 >> 11;
    const int jbase = row0 & 2047;

    if (tid < 16) { __stcg(&g_u[row0 + tid], 1.0f); __stcg(&g_v[row0 + tid], 1.0f); }
    grid_sync(gen);

    for (int it = 0; it < 10; it++) {
        for (int j = tid; j < NT; j += 256) sv[j] = __ldcg(&g_v[bb*NT + j]);
        __syncthreads();
        #pragma unroll
        for (int rr = 0; rr < 2; rr++) {
            int r = row0 + w*2 + rr;
            const float* Pr = g_P + (size_t)r * NT;
            float s = 0.f;
            #pragma unroll 8
            for (int j = lane; j < NT; j += 32) s += Pr[j] * sv[j];
            #pragma unroll
            for (int o = 16; o > 0; o >>= 1) s += __shfl_xor_sync(0xffffffffu, s, o);
            if (lane == 0) {
                float u = __ldcg(&g_u[r]);
                __stcg(&g_u[r], u / (u * s + EPSF));
            }
        }
        grid_sync(gen);

        for (int i = tid; i < NT; i += 256) sv[i] = __ldcg(&g_u[bb*NT + i]);
        __syncthreads();
        {
            int c = tid & 15, rg = tid >> 4;
            const float* Pc = g_P + (size_t)bb*NT*NT + jbase + c;
            float s = 0.f;
            #pragma unroll 8
            for (int i = rg; i < NT; i += 16) s += Pc[(size_t)i*NT] * sv[i];
            red[tid] = s; __syncthreads();
            if (tid < 128) red[tid] += red[tid+128];
            __syncthreads();
            if (tid < 64)  red[tid] += red[tid+64];
            __syncthreads();
            if (tid < 32)  red[tid] += red[tid+32];
            __syncthreads();
            if (tid < 16) {
                float tot = red[tid] + red[tid+16];
                int jj = bb*NT + jbase + tid;
                float v = __ldcg(&g_v[jj]);
                __stcg(&g_v[jj], v / (v * tot + EPSF));
            }
            __syncthreads();
        }
        grid_sync(gen);
    }

    for (int j = tid; j < NT; j += 256) sv[j] = __ldcg(&g_v[bb*NT + j]);
    __syncthreads();
    #pragma unroll
    for (int rr = 0; rr < 2; rr++) {
        int r = row0 + w*2 + rr;
        const float* Pr = g_P + (size_t)r * NT;
        float best = -INFINITY; int bj = NT;
        for (int j = lane; j < NT; j += 32) {
            float val = Pr[j] * sv[j];
            if (val > best) { best = val; bj = j; }
        }
        #pragma unroll
        for (int o = 16; o > 0; o >>= 1) {
            float ob = __shfl_xor_sync(0xffffffffu, best, o);
            int   oj = __shfl_xor_sync(0xffffffffu, bj, o);
            if (ob > best || (ob == best && oj < bj)) { best = ob; bj = oj; }
        }
        if (lane == 0) outp[r] = (float)perm[bb*NT + bj];
    }
}

// ---------------------------------------------------------------------------
__global__ __launch_bounds__(256)
void cert_kernel(const float* __restrict__ cert, const float* __restrict__ ctemp,
                 float* __restrict__ out)
{
    const int idx = blockIdx.x * 256 + threadIdx.x;
    const int b = idx >> 11, i = idx & 2047;
    float s = 0.f;
    #pragma unroll
    for (int h = 0; h < H; h++) {
        size_t o = (size_t)(b*H + h)*NT + i;
        float Z = g_Z[o];
        s += logf(Z) - g_T[o] / Z;
    }
    float ent = s * (1.0f / 16.0f);
    float z = ctemp[0] * (logf(2048.0f) - ent);
    out[idx] = fmaxf(cert[idx], 1.0f / (1.0f + expf(-z)));
}

extern "C" void kernel_launch(void* const* d_in, const int* in_sizes, int n_in,
                              void* d_out, int out_size)
{
    const float* x     = (const float*)d_in[0];
    const float* cert  = (const float*)d_in[1];
    const int*   perm  = (const int*)  d_in[2];
    const float* Wq    = (const float*)d_in[3];
    const float* bq    = (const float*)d_in[4];
    const float* Wk    = (const float*)d_in[5];
    const float* bk    = (const float*)d_in[6];
    const float* Wv    = (const float*)d_in[7];
    const float* bvv   = (const float*)d_in[8];
    const float* Wo    = (const float*)d_in[9];
    const float* bo    = (const float*)d_in[10];
    const float* pbs   = (const float*)d_in[11];
    const float* ctemp = (const float*)d_in[12];
    float* out = (float*)d_out;

    __half *pxh, *pWqkv, *pWoh, *pCtx;
    cudaGetSymbolAddress((void**)&pxh,   g_xh);
    cudaGetSymbolAddress((void**)&pWqkv, g_Wqkvh);
    cudaGetSymbolAddress((void**)&pWoh,  g_Woh);
    cudaGetSymbolAddress((void**)&pCtx,  g_ctxh);

    const int SMEM_H = 2*3*128*40*2;   // 61440 B
    cudaFuncSetAttribute(gemm_h, cudaFuncAttributeMaxDynamicSharedMemorySize, SMEM_H);

    const int M = B * NT;                  // 4096

    // one-time fp16 conversions
    cvt_f2h<<<(M*DM/4 + 255)/256, 256>>>(x,  pxh,           M*DM/4);
    cvt_f2h<<<(DM*DM/4 + 255)/256, 256>>>(Wq, pWqkv,          DM*DM/4);
    cvt_f2h<<<(DM*DM/4 + 255)/256, 256>>>(Wk, pWqkv + DM*DM,  DM*DM/4);
    cvt_f2h<<<(DM*DM/4 + 255)/256, 256>>>(Wv, pWqkv + 2*DM*DM,DM*DM/4);
    cvt_f2h<<<(DM*DM/4 + 255)/256, 256>>>(Wo, pWoh,           DM*DM/4);
    concat_bias<<<12, 256>>>(bq, bk, bvv);

    // fused QKV projection (fp16 mma)
    dim3 gQKV(3*DM/128, M/128);            // (24, 32)
    gemm_h<<<gQKV, 256, SMEM_H>>>(pxh, pWqkv, nullptr, nullptr, 3*DM, DM, 3);

    dim3 gS(NT/128, B*H);                  // (16, 32)
    scores_exp_mma<<<gS, 256>>>(pbs, perm);

    av_mma<<<gS, 256>>>();

    // output projection (fp16 mma, fp32 out)
    dim3 gO(DM/128, M/128);                // (8, 32)
    gemm_h<<<gO, 256, SMEM_H>>>(pCtx, pWoh, bo, out, DM, DM, 0);

    cert_kernel<<<(B*NT)/256, 256>>>(cert, ctemp, out + (size_t)M*DM);

    build_P_kernel<<<4096, 256>>>();
    sinkhorn_persist<<<NB_SINK, 256>>>(perm, out + (size_t)M*DM + B*NT);
}

// round 12
// speedup vs baseline: 1.6606x; 1.1222x over previous
#include <cuda_runtime.h>
#include <cuda_fp16.h>
#include <math.h>

#define B   2
#define NT  2048
#define DM  1024
#define H   16
#define HD  64
#define EPSF 1e-10f
#define NB_SINK 256

__device__ __half g_xh[(size_t)B*NT*DM];
__device__ __half g_Wqkvh[(size_t)3*DM*DM];
__device__ __half g_Woh[(size_t)DM*DM];
__device__ float  g_bqkv[3*DM];
__device__ __half g_Qh[(size_t)B*H*NT*HD];          // [bh][tok][hd]
__device__ __half g_Kh[(size_t)B*H*NT*HD];          // [bh][tok][hd]
__device__ __half g_Vh[(size_t)B*H*NT*HD];          // [bh][hd][tok]
__device__ __half g_Eh[(size_t)B*H*NT*NT];          // exp(scores), fp16
__device__ __half g_ctxh[(size_t)B*NT*DM];
__device__ float g_P[(size_t)B*NT*NT];
__device__ float g_Z[(size_t)B*H*NT];
__device__ float g_T[(size_t)B*H*NT];
__device__ float g_Zi[(size_t)B*H*NT];
__device__ float g_u[B*NT];
__device__ float g_v[B*NT];
__device__ float g_colpart[(size_t)B*128*NT];
__device__ unsigned g_barcount = 0;
__device__ unsigned g_bargen = 0;

__device__ __forceinline__ void mma_f16(float4 &c,
    unsigned a0, unsigned a1, unsigned a2, unsigned a3,
    unsigned b0, unsigned b1)
{
    asm("mma.sync.aligned.m16n8k16.row.col.f32.f16.f16.f32 "
        "{%0,%1,%2,%3},{%4,%5,%6,%7},{%8,%9},{%0,%1,%2,%3};"
        : "+f"(c.x), "+f"(c.y), "+f"(c.z), "+f"(c.w)
        : "r"(a0), "r"(a1), "r"(a2), "r"(a3), "r"(b0), "r"(b1));
}
__device__ __forceinline__ void cp16(unsigned d, const void* s){
    asm volatile("cp.async.cg.shared.global [%0], [%1], 16;\n" :: "r"(d), "l"(s));
}
__device__ __forceinline__ void cp_commit(){ asm volatile("cp.async.commit_group;\n"); }
__device__ __forceinline__ void cp_wait1(){ asm volatile("cp.async.wait_group 1;\n" ::: "memory"); }
__device__ __forceinline__ void cp_wait0(){ asm volatile("cp.async.wait_group 0;\n" ::: "memory"); }

// ---------------------------------------------------------------------------
// merged fp32->fp16 conversion for x, Wq, Wk, Wv, Wo
// ---------------------------------------------------------------------------
__global__ __launch_bounds__(256)
void cvt_all(const float* __restrict__ x,  const float* __restrict__ Wq,
             const float* __restrict__ Wk, const float* __restrict__ Wv,
             const float* __restrict__ Wo)
{
    int i = blockIdx.x * 256 + threadIdx.x;   // 0 .. 2097151 (float4 units)
    const float* src; __half* dst; int off;
    if (i < 1048576) { src = x; dst = g_xh; off = i; }
    else {
        int j = i - 1048576;
        int seg = j >> 18;                    // 0..3
        off = j & 262143;
        src = (seg == 0) ? Wq : (seg == 1) ? Wk : (seg == 2) ? Wv : Wo;
        dst = (seg == 3) ? g_Woh : g_Wqkvh + (size_t)seg * DM * DM;
    }
    float4 v = ((const float4*)src)[off];
    ((__half2*)dst)[2*off]   = __floats2half2_rn(v.x, v.y);
    ((__half2*)dst)[2*off+1] = __floats2half2_rn(v.z, v.w);
}

__global__ __launch_bounds__(256)
void concat_bias(const float* __restrict__ bq, const float* __restrict__ bk,
                 const float* __restrict__ bv)
{
    int i = blockIdx.x * 256 + threadIdx.x;
    float v = (i < 1024) ? bq[i] : (i < 2048 ? bk[i-1024] : bv[i-2048]);
    g_bqkv[i] = v;
}

// ---------------------------------------------------------------------------
// fp16 GEMM: C[m][e] = sum_k A[m][k]*W[e][k] + bias[e].  128x128, BK=32.
// omode 0: float row-major out; omode 3: fused QKV out (Q/K head, V transposed)
// ---------------------------------------------------------------------------
__global__ __launch_bounds__(256, 2)
void gemm_h(const __half* __restrict__ A, const __half* __restrict__ W,
            const float* __restrict__ bias, float* __restrict__ C,
            int N, int K, int omode)
{
    extern __shared__ __half smh[];
    __half* Asm = smh;                 // [3][128][40]
    __half* Bsm = smh + 3*128*40;
    const unsigned sA = (unsigned)__cvta_generic_to_shared(Asm);
    const unsigned sB = (unsigned)__cvta_generic_to_shared(Bsm);

    const int tid = threadIdx.x, lane = tid & 31, warp = tid >> 5;
    const int gid = lane >> 2, tig = lane & 3;
    const int wm = warp & 1, wn = warp >> 1;
    const int bm0 = blockIdx.y * 128, bn0 = blockIdx.x * 128;
    const int lr = tid >> 1, lkq = (tid & 1) * 16;
    const __half* Ag = A + (size_t)(bm0 + lr) * K + lkq;
    const __half* Wg = W + (size_t)(bn0 + lr) * K + lkq;
    const int NCH = K / 32;

    float4 acc[4][4];
    #pragma unroll
    for (int i = 0; i < 4; i++)
        #pragma unroll
        for (int j = 0; j < 4; j++) acc[i][j] = make_float4(0.f,0.f,0.f,0.f);

    auto issue = [&](int cc){
        int st = cc % 3, k0 = cc * 32;
        unsigned da = sA + (unsigned)(((st*128 + lr)*40 + lkq)*2);
        cp16(da,      Ag + k0);
        cp16(da + 16, Ag + k0 + 8);
        unsigned db = sB + (unsigned)(((st*128 + lr)*40 + lkq)*2);
        cp16(db,      Wg + k0);
        cp16(db + 16, Wg + k0 + 8);
        cp_commit();
    };

    issue(0); issue(1);

    for (int c = 0; c < NCH; c++) {
        if (c + 1 < NCH) cp_wait1(); else cp_wait0();
        __syncthreads();
        if (c + 2 < NCH) issue(c + 2);
        const __half* As_ = Asm + (c % 3)*128*40;
        const __half* Bs_ = Bsm + (c % 3)*128*40;
        #pragma unroll
        for (int ks = 0; ks < 2; ks++) {
            const int kb = ks * 16;
            unsigned af[4][4];
            #pragma unroll
            for (int mt = 0; mt < 4; mt++) {
                int m = wm*64 + mt*16 + gid;
                af[mt][0] = *(const unsigned*)&As_[m*40     + kb + 2*tig];
                af[mt][1] = *(const unsigned*)&As_[(m+8)*40 + kb + 2*tig];
                af[mt][2] = *(const unsigned*)&As_[m*40     + kb + 2*tig + 8];
                af[mt][3] = *(const unsigned*)&As_[(m+8)*40 + kb + 2*tig + 8];
            }
            #pragma unroll
            for (int nt = 0; nt < 4; nt++) {
                int n = wn*32 + nt*8 + gid;
                unsigned b0 = *(const unsigned*)&Bs_[n*40 + kb + 2*tig];
                unsigned b1 = *(const unsigned*)&Bs_[n*40 + kb + 2*tig + 8];
                #pragma unroll
                for (int mt = 0; mt < 4; mt++)
                    mma_f16(acc[mt][nt], af[mt][0],af[mt][1],af[mt][2],af[mt][3], b0, b1);
            }
        }
    }

    #pragma unroll
    for (int mt = 0; mt < 4; mt++) {
        int r0 = bm0 + wm*64 + mt*16 + gid;
        #pragma unroll
        for (int nt = 0; nt < 4; nt++) {
            int c0 = bn0 + wn*32 + nt*8 + tig*2;
            float bx, by;
            if (omode == 3) { bx = g_bqkv[c0]; by = g_bqkv[c0+1]; }
            else            { bx = bias[c0];   by = bias[c0+1];   }
            float2 lo = make_float2(acc[mt][nt].x + bx, acc[mt][nt].y + by);
            float2 hi = make_float2(acc[mt][nt].z + bx, acc[mt][nt].w + by);
            if (omode == 0) {
                float* p = C + (size_t)r0*N + c0;
                *(float2*)p = lo;
                *(float2*)(p + 8*(size_t)N) = hi;
            } else {
                int which = c0 >> 10;
                int e = c0 & 1023;
                int bb = r0 >> 11, tok = r0 & 2047, hh = e >> 6, hd = e & 63;
                size_t bh = (size_t)(bb*H + hh);
                if (which == 0) {
                    __half* p = g_Qh + (bh*NT + tok)*HD + hd;
                    *(__half2*)p          = __floats2half2_rn(lo.x, lo.y);
                    *(__half2*)(p + 8*HD) = __floats2half2_rn(hi.x, hi.y);
                } else if (which == 1) {
                    __half* p = g_Kh + (bh*NT + tok)*HD + hd;
                    *(__half2*)p          = __floats2half2_rn(lo.x, lo.y);
                    *(__half2*)(p + 8*HD) = __floats2half2_rn(hi.x, hi.y);
                } else {
                    __half* p = g_Vh + (bh*HD + hd)*NT + tok;
                    p[0]      = __float2half_rn(lo.x);
                    p[NT]     = __float2half_rn(lo.y);
                    p[8]      = __float2half_rn(hi.x);
                    p[NT + 8] = __float2half_rn(hi.y);
                }
            }
        }
    }
}

// ---------------------------------------------------------------------------
// Fused scores + exp + row Z/T/Zi.  fp16 mma; BK=32 chunks (2 per j-tile).
// dyn smem: pfi/pfj (1 KB) | Qs[128][72]h | Ks[3][128][40]h  = 50176 B
// ---------------------------------------------------------------------------
__global__ __launch_bounds__(256, 2)
void scores_exp_mma(const float* __restrict__ pbs, const int* __restrict__ perm)
{
    extern __shared__ char smraw[];
    float* pfi = (float*)smraw;
    float* pfj = pfi + 128;
    __half* Qs = (__half*)(smraw + 1024);          // [128][72]
    __half* Ks = Qs + 128*72;                      // [3][128][40]
    const unsigned sK = (unsigned)__cvta_generic_to_shared(Ks);

    const int tid = threadIdx.x, lane = tid & 31, warp = tid >> 5;
    const int gid = lane >> 2, tig = lane & 3;
    const int wm = warp & 1, wn = warp >> 1;
    const int bh = blockIdx.y, b = bh >> 4, h = bh & 15;
    const int bi0 = blockIdx.x * 128;
    const float pb = fabsf(pbs[h]);

    const __half* Qg = g_Qh + ((size_t)bh*NT + bi0)*HD;
    const __half* Kbase = g_Kh + (size_t)bh*NT*HD;
    const int lr = tid >> 1;
    const int lq8 = (tid & 1) * 8;      // Q staging
    const int lk16 = (tid & 1) * 16;    // K cp.async

    #pragma unroll
    for (int cq = 0; cq < 4; cq++) {
        int kk = lq8 + cq*16;
        uint4 q = *(const uint4*)(Qg + (size_t)lr*HD + kk);
        *(uint4*)&Qs[lr*72 + kk] = q;
    }
    if (tid < 128) pfi[tid] = (float)perm[b*NT + bi0 + tid];

    float Zr[8] = {0,0,0,0,0,0,0,0};
    float Tr[8] = {0,0,0,0,0,0,0,0};

    auto issue = [&](int cc){
        int st = cc % 3, jt = cc >> 1, kc = (cc & 1) * 32;
        unsigned d = sK + (unsigned)(((st*128 + lr)*40 + lk16)*2);
        const __half* s = Kbase + (size_t)(jt*128 + lr)*HD + kc + lk16;
        cp16(d, s); cp16(d + 16, s + 8);
        cp_commit();
    };

    issue(0); issue(1);
    const int NCH = 32;

    for (int jt = 0; jt < 16; jt++) {
        const int j0 = jt * 128;
        float4 acc[4][4];
        #pragma unroll
        for (int i = 0; i < 4; i++)
            #pragma unroll
            for (int j = 0; j < 4; j++) acc[i][j] = make_float4(0.f,0.f,0.f,0.f);

        #pragma unroll
        for (int k2 = 0; k2 < 2; k2++) {
            const int c = jt*2 + k2;
            if (c + 1 < NCH) cp_wait1(); else cp_wait0();
            __syncthreads();
            if (c + 2 < NCH) issue(c + 2);
            if (k2 == 0 && tid < 128) pfj[tid] = (float)perm[b*NT + j0 + tid];
            const __half* Ks_ = Ks + (c % 3)*128*40;
            const int kc = k2 * 32;

            #pragma unroll
            for (int ks = 0; ks < 2; ks++) {
                const int kb = ks * 16;
                unsigned af[4][4];
                #pragma unroll
                for (int mt = 0; mt < 4; mt++) {
                    int m = wm*64 + mt*16 + gid;
                    af[mt][0] = *(const unsigned*)&Qs[m*72     + kc + kb + 2*tig];
                    af[mt][1] = *(const unsigned*)&Qs[(m+8)*72 + kc + kb + 2*tig];
                    af[mt][2] = *(const unsigned*)&Qs[m*72     + kc + kb + 2*tig + 8];
                    af[mt][3] = *(const unsigned*)&Qs[(m+8)*72 + kc + kb + 2*tig + 8];
                }
                #pragma unroll
                for (int nt = 0; nt < 4; nt++) {
                    int n = wn*32 + nt*8 + gid;
                    unsigned b0 = *(const unsigned*)&Ks_[n*40 + kb + 2*tig];
                    unsigned b1 = *(const unsigned*)&Ks_[n*40 + kb + 2*tig + 8];
                    #pragma unroll
                    for (int mt = 0; mt < 4; mt++)
                        mma_f16(acc[mt][nt], af[mt][0],af[mt][1],af[mt][2],af[mt][3], b0, b1);
                }
            }
        }

        #pragma unroll
        for (int mt = 0; mt < 4; mt++) {
            int rl = wm*64 + mt*16 + gid;
            float pa = pfi[rl], pc = pfi[rl+8];
            #pragma unroll
            for (int nt = 0; nt < 4; nt++) {
                int cl = wn*32 + nt*8 + tig*2;
                float d0 = pfj[cl], d1 = pfj[cl+1];
                float4 a = acc[mt][nt];
                float s00 = a.x*0.125f - fabsf(pa - d0)*pb;
                float s01 = a.y*0.125f - fabsf(pa - d1)*pb;
                float s10 = a.z*0.125f - fabsf(pc - d0)*pb;
                float s11 = a.w*0.125f - fabsf(pc - d1)*pb;
                __half2 hA = __floats2half2_rn(__expf(s00), __expf(s01));
                __half2 hB = __floats2half2_rn(__expf(s10), __expf(s11));
                float2 fA = __half22float2(hA);
                float2 fB = __half22float2(hB);
                Zr[mt*2]   += fA.x + fA.y;  Tr[mt*2]   += s00*fA.x + s01*fA.y;
                Zr[mt*2+1] += fB.x + fB.y;  Tr[mt*2+1] += s10*fB.x + s11*fB.y;
                size_t base = ((size_t)bh*NT + bi0 + rl)*NT + j0 + cl;
                *(__half2*)(g_Eh + base)        = hA;
                *(__half2*)(g_Eh + base + 8*NT) = hB;
            }
        }
    }

    // packed Z+T reduction (single smem round); Qs region = 4608 floats
    float* redZ = (float*)Qs;
    float* redT = redZ + 2048;
    const int pcol = wn*4 + tig;
    __syncthreads();
    #pragma unroll
    for (int mt = 0; mt < 4; mt++) {
        int r0 = wm*64 + mt*16 + gid;
        redZ[pcol*128 + r0]     = Zr[mt*2];
        redZ[pcol*128 + r0 + 8] = Zr[mt*2+1];
        redT[pcol*128 + r0]     = Tr[mt*2];
        redT[pcol*128 + r0 + 8] = Tr[mt*2+1];
    }
    __syncthreads();
    if (tid < 128) {
        float sz = 0.f, st = 0.f;
        #pragma unroll
        for (int t = 0; t < 16; t++) { sz += redZ[t*128 + tid]; st += redT[t*128 + tid]; }
        g_Z[(size_t)bh*NT + bi0 + tid]  = sz;
        g_Zi[(size_t)bh*NT + bi0 + tid] = 1.0f / sz;
        g_T[(size_t)bh*NT + bi0 + tid]  = st;
    }
}

// ---------------------------------------------------------------------------
// ctx(half) = (E @ V) / Z.  fp16 mma; BK=32.  static smem ~47 KB.
// ---------------------------------------------------------------------------
__global__ __launch_bounds__(256, 2)
void av_mma()
{
    __shared__ __half Es[3][128][40];
    __shared__ __half Vs[3][64][40];
    __shared__ float zin[128];
    const unsigned sE = (unsigned)__cvta_generic_to_shared(&Es[0][0][0]);
    const unsigned sV = (unsigned)__cvta_generic_to_shared(&Vs[0][0][0]);

    const int tid = threadIdx.x, lane = tid & 31, warp = tid >> 5;
    const int gid = lane >> 2, tig = lane & 3;
    const int wm = warp >> 1, wn = warp & 1;
    const int bh = blockIdx.y, b = bh >> 4, h = bh & 15;
    const int bi0 = blockIdx.x * 128;

    const int lr = tid >> 1, lk16 = (tid & 1) * 16;
    const __half* Eg = g_Eh + ((size_t)bh*NT + bi0 + lr)*NT + lk16;
    const __half* Vg = g_Vh + (size_t)bh*HD*NT;
    const int vr = (tid & 127) >> 1;

    if (tid < 128) zin[tid] = g_Zi[(size_t)bh*NT + bi0 + tid];

    float4 acc[2][4];
    #pragma unroll
    for (int i = 0; i < 2; i++)
        #pragma unroll
        for (int j = 0; j < 4; j++) acc[i][j] = make_float4(0.f,0.f,0.f,0.f);

    auto issue = [&](int cc){
        int st = cc % 3, k0 = cc * 32;
        unsigned dE = sE + (unsigned)(((st*128 + lr)*40 + lk16)*2);
        cp16(dE,      Eg + k0);
        cp16(dE + 16, Eg + k0 + 8);
        if (tid < 128) {
            unsigned dV = sV + (unsigned)(((st*64 + vr)*40 + lk16)*2);
            const __half* s = Vg + (size_t)vr*NT + k0 + lk16;
            cp16(dV, s); cp16(dV + 16, s + 8);
        }
        cp_commit();
    };

    issue(0); issue(1);
    const int NCH = NT / 32;   // 64

    for (int c = 0; c < NCH; c++) {
        if (c + 1 < NCH) cp_wait1(); else cp_wait0();
        __syncthreads();
        if (c + 2 < NCH) issue(c + 2);
        const __half* Es_ = &Es[c % 3][0][0];
        const __half* Vs_ = &Vs[c % 3][0][0];

        #pragma unroll
        for (int ks = 0; ks < 2; ks++) {
            const int kb = ks * 16;
            unsigned af[2][4];
            #pragma unroll
            for (int mt = 0; mt < 2; mt++) {
                int m = wm*32 + mt*16 + gid;
                af[mt][0] = *(const unsigned*)&Es_[m*40     + kb + 2*tig];
                af[mt][1] = *(const unsigned*)&Es_[(m+8)*40 + kb + 2*tig];
                af[mt][2] = *(const unsigned*)&Es_[m*40     + kb + 2*tig + 8];
                af[mt][3] = *(const unsigned*)&Es_[(m+8)*40 + kb + 2*tig + 8];
            }
            #pragma unroll
            for (int nt = 0; nt < 4; nt++) {
                int n = wn*32 + nt*8 + gid;
                unsigned b0 = *(const unsigned*)&Vs_[n*40 + kb + 2*tig];
                unsigned b1 = *(const unsigned*)&Vs_[n*40 + kb + 2*tig + 8];
                #pragma unroll
                for (int mt = 0; mt < 2; mt++)
                    mma_f16(acc[mt][nt], af[mt][0],af[mt][1],af[mt][2],af[mt][3], b0, b1);
            }
        }
    }

    #pragma unroll
    for (int mt = 0; mt < 2; mt++) {
        int rl = wm*32 + mt*16 + gid;
        float z0 = zin[rl], z1 = zin[rl+8];
        #pragma unroll
        for (int nt = 0; nt < 4; nt++) {
            int cl = wn*32 + nt*8 + tig*2;
            float4 a = acc[mt][nt];
            size_t base = ((size_t)b*NT + bi0 + rl)*DM + h*HD + cl;
            *(__half2*)(g_ctxh + base)        = __floats2half2_rn(a.x*z0, a.y*z0);
            *(__half2*)(g_ctxh + base + 8*DM) = __floats2half2_rn(a.z*z1, a.w*z1);
        }
    }
}

// ---------------------------------------------------------------------------
// P raw: (mean_h attention + EPS)^10, reading fp16 E 8-wide.
// ---------------------------------------------------------------------------
__global__ __launch_bounds__(256)
void build_P_kernel()
{
    size_t idx8 = ((size_t)blockIdx.x * 256 + threadIdx.x) * 8;
    size_t b = idx8 / ((size_t)NT*NT);
    size_t rem = idx8 - b * (size_t)NT*NT;
    int i = (int)(rem >> 11);
    float s[8] = {0,0,0,0,0,0,0,0};
    #pragma unroll
    for (int h = 0; h < H; h++) {
        uint4 raw = *(const uint4*)&g_Eh[(size_t)(b*H + h)*NT*NT + rem];
        float zi = g_Zi[(size_t)(b*H + h)*NT + i];
        float2 p0 = __half22float2(*(__half2*)&raw.x);
        float2 p1 = __half22float2(*(__half2*)&raw.y);
        float2 p2 = __half22float2(*(__half2*)&raw.z);
        float2 p3 = __half22float2(*(__half2*)&raw.w);
        s[0] += p0.x*zi; s[1] += p0.y*zi; s[2] += p1.x*zi; s[3] += p1.y*zi;
        s[4] += p2.x*zi; s[5] += p2.y*zi; s[6] += p3.x*zi; s[7] += p3.y*zi;
    }
    float o[8];
    #pragma unroll
    for (int k = 0; k < 8; k++)
        o[k] = expf(logf(s[k] * (1.0f/16.0f) + EPSF) * 10.0f);
    *(float4*)&g_P[idx8]     = make_float4(o[0],o[1],o[2],o[3]);
    *(float4*)&g_P[idx8 + 4] = make_float4(o[4],o[5],o[6],o[7]);
}

// ---------------------------------------------------------------------------
// Persistent Sinkhorn: fused row-update + coalesced partial colsums, u in smem.
// ---------------------------------------------------------------------------
__device__ __forceinline__ void grid_sync(unsigned &gen)
{
    __syncthreads();
    if (threadIdx.x == 0) {
        gen++;
        __threadfence();
        unsigned old = atomicAdd(&g_barcount, 1);
        if (old == NB_SINK - 1) {
            atomicExch(&g_barcount, 0);
            atomicExch(&g_bargen, gen);
        } else {
            while (*(volatile unsigned*)&g_bargen < gen) __nanosleep(64);
        }
    }
    __syncthreads();
}

__global__ __launch_bounds__(256)
void sinkhorn_persist(const int* __restrict__ perm, float* __restrict__ outp)
{
    __shared__ float sv[NT];
    __shared__ float su[16];
    __shared__ float red[256];
    const int tid = threadIdx.x, bk = blockIdx.x;
    const int lane = tid & 31, w = tid >> 5;
    unsigned gen = *(volatile unsigned*)&g_bargen;

    const int row0 = bk * 16;
    const int bb = row0 >> 11;
    const int blkb = bk & 127;
    const int jbase = blkb * 16;
    float* cp = g_colpart + ((size_t)bb*128 + blkb)*NT;

    if (tid < 16) {
        su[tid] = 1.0f;
        __stcg(&g_v[bb*NT + jbase + tid], 1.0f);
    }
    grid_sync(gen);

    for (int it = 0; it < 10; it++) {
        for (int j = tid; j < NT; j += 256) sv[j] = __ldcg(&g_v[bb*NT + j]);
        __syncthreads();
        // row update: u_i = u_i / (u_i*(Pv)_i + eps), u resident in smem
        #pragma unroll
        for (int rr = 0; rr < 2; rr++) {
            int rl = w*2 + rr;
            const float* Pr = g_P + (size_t)(row0 + rl)*NT;
            float s = 0.f;
            #pragma unroll 8
            for (int j = lane; j < NT; j += 32) s += Pr[j] * sv[j];
            #pragma unroll
            for (int o = 16; o > 0; o >>= 1) s += __shfl_xor_sync(0xffffffffu, s, o);
            if (lane == 0) { float u = su[rl]; su[rl] = u / (u * s + EPSF); }
        }
        __syncthreads();
        // partial column sums with new u (row-major coalesced second sweep)
        float pa[8] = {0,0,0,0,0,0,0,0};
        #pragma unroll
        for (int i = 0; i < 16; i++) {
            float ui = su[i];
            const float* Pr = g_P + (size_t)(row0 + i)*NT;
            #pragma unroll
            for (int k = 0; k < 8; k++) pa[k] += ui * Pr[tid + k*256];
        }
        #pragma unroll
        for (int k = 0; k < 8; k++) cp[tid + k*256] = pa[k];
        grid_sync(gen);
        // combine for this block's 16 owned columns
        {
            int c = tid & 15, grp = tid >> 4;
            const float* base = g_colpart + (size_t)bb*128*NT + jbase + c;
            float s = 0.f;
            #pragma unroll
            for (int kk = 0; kk < 8; kk++)
                s += __ldcg(&base[(size_t)(grp*8 + kk)*NT]);
            red[tid] = s; __syncthreads();
            if (tid < 128) red[tid] += red[tid+128];
            __syncthreads();
            if (tid < 64)  red[tid] += red[tid+64];
            __syncthreads();
            if (tid < 32)  red[tid] += red[tid+32];
            __syncthreads();
            if (tid < 16) {
                float tot = red[tid] + red[tid+16];
                int jj = bb*NT + jbase + tid;
                float v = __ldcg(&g_v[jj]);
                __stcg(&g_v[jj], v / (v * tot + EPSF));
            }
        }
        grid_sync(gen);
    }

    // argmax_j P_ij*v_j (first max wins) + gather
    for (int j = tid; j < NT; j += 256) sv[j] = __ldcg(&g_v[bb*NT + j]);
    __syncthreads();
    #pragma unroll
    for (int rr = 0; rr < 2; rr++) {
        int r = row0 + w*2 + rr;
        const float* Pr = g_P + (size_t)r * NT;
        float best = -INFINITY; int bj = NT;
        for (int j = lane; j < NT; j += 32) {
            float val = Pr[j] * sv[j];
            if (val > best) { best = val; bj = j; }
        }
        #pragma unroll
        for (int o = 16; o > 0; o >>= 1) {
            float ob = __shfl_xor_sync(0xffffffffu, best, o);
            int   oj = __shfl_xor_sync(0xffffffffu, bj, o);
            if (ob > best || (ob == best && oj < bj)) { best = ob; bj = oj; }
        }
        if (lane == 0) outp[r] = (float)perm[bb*NT + bj];
    }
}

// ---------------------------------------------------------------------------
__global__ __launch_bounds__(256)
void cert_kernel(const float* __restrict__ cert, const float* __restrict__ ctemp,
                 float* __restrict__ out)
{
    const int idx = blockIdx.x * 256 + threadIdx.x;
    const int b = idx >> 11, i = idx & 2047;
    float s = 0.f;
    #pragma unroll
    for (int h = 0; h < H; h++) {
        size_t o = (size_t)(b*H + h)*NT + i;
        float Z = g_Z[o];
        s += logf(Z) - g_T[o] / Z;
    }
    float ent = s * (1.0f / 16.0f);
    float z = ctemp[0] * (logf(2048.0f) - ent);
    out[idx] = fmaxf(cert[idx], 1.0f / (1.0f + expf(-z)));
}

extern "C" void kernel_launch(void* const* d_in, const int* in_sizes, int n_in,
                              void* d_out, int out_size)
{
    const float* x     = (const float*)d_in[0];
    const float* cert  = (const float*)d_in[1];
    const int*   perm  = (const int*)  d_in[2];
    const float* Wq    = (const float*)d_in[3];
    const float* bq    = (const float*)d_in[4];
    const float* Wk    = (const float*)d_in[5];
    const float* bk    = (const float*)d_in[6];
    const float* Wv    = (const float*)d_in[7];
    const float* bvv   = (const float*)d_in[8];
    const float* Wo    = (const float*)d_in[9];
    const float* bo    = (const float*)d_in[10];
    const float* pbs   = (const float*)d_in[11];
    const float* ctemp = (const float*)d_in[12];
    float* out = (float*)d_out;

    __half *pxh, *pWqkv, *pWoh, *pCtx;
    cudaGetSymbolAddress((void**)&pxh,   g_xh);
    cudaGetSymbolAddress((void**)&pWqkv, g_Wqkvh);
    cudaGetSymbolAddress((void**)&pWoh,  g_Woh);
    cudaGetSymbolAddress((void**)&pCtx,  g_ctxh);

    const int SMEM_H = 2*3*128*40*2;                 // 61440 B
    const int SMEM_S = 1024 + 128*72*2 + 3*128*40*2; // 50176 B
    cudaFuncSetAttribute(gemm_h, cudaFuncAttributeMaxDynamicSharedMemorySize, SMEM_H);
    cudaFuncSetAttribute(scores_exp_mma, cudaFuncAttributeMaxDynamicSharedMemorySize, SMEM_S);

    const int M = B * NT;                  // 4096

    cvt_all<<<8192, 256>>>(x, Wq, Wk, Wv, Wo);
    concat_bias<<<12, 256>>>(bq, bk, bvv);

    dim3 gQKV(3*DM/128, M/128);            // (24, 32)
    gemm_h<<<gQKV, 256, SMEM_H>>>(pxh, pWqkv, nullptr, nullptr, 3*DM, DM, 3);

    dim3 gS(NT/128, B*H);                  // (16, 32)
    scores_exp_mma<<<gS, 256, SMEM_S>>>(pbs, perm);

    av_mma<<<gS, 256>>>();

    dim3 gO(DM/128, M/128);                // (8, 32)
    gemm_h<<<gO, 256, SMEM_H>>>(pCtx, pWoh, bo, out, DM, DM, 0);

    cert_kernel<<<(B*NT)/256, 256>>>(cert, ctemp, out + (size_t)M*DM);

    build_P_kernel<<<4096, 256>>>();
    sinkhorn_persist<<<NB_SINK, 256>>>(perm, out + (size_t)M*DM + B*NT);
}

// round 13
// speedup vs baseline: 1.7458x; 1.0513x over previous
#include <cuda_runtime.h>
#include <cuda_fp16.h>
#include <math.h>

#define B   2
#define NT  2048
#define DM  1024
#define H   16
#define HD  64
#define EPSF 1e-10f
#define NB_SINK 256

__device__ __half g_xh[(size_t)B*NT*DM];
__device__ __half g_Wqkvh[(size_t)3*DM*DM];
__device__ __half g_Woh[(size_t)DM*DM];
__device__ float  g_bqkv[3*DM];
__device__ __half g_Qh[(size_t)B*H*NT*HD];          // [bh][tok][hd]
__device__ __half g_Kh[(size_t)B*H*NT*HD];          // [bh][tok][hd]
__device__ __half g_Vh[(size_t)B*H*NT*HD];          // [bh][hd][tok]
__device__ __half g_Eh[(size_t)B*H*NT*NT];          // exp(scores), fp16
__device__ __half g_ctxh[(size_t)B*NT*DM];
__device__ float g_P[(size_t)B*NT*NT];
__device__ float g_Z[(size_t)B*H*NT];
__device__ float g_T[(size_t)B*H*NT];
__device__ float g_Zi[(size_t)B*H*NT];
__device__ float g_u[B*NT];
__device__ float g_v[B*NT];
__device__ float g_colpart[(size_t)B*128*NT];
__device__ unsigned g_barcount = 0;
__device__ unsigned g_bargen = 0;

__device__ __forceinline__ void mma_f16(float4 &c,
    unsigned a0, unsigned a1, unsigned a2, unsigned a3,
    unsigned b0, unsigned b1)
{
    asm("mma.sync.aligned.m16n8k16.row.col.f32.f16.f16.f32 "
        "{%0,%1,%2,%3},{%4,%5,%6,%7},{%8,%9},{%0,%1,%2,%3};"
        : "+f"(c.x), "+f"(c.y), "+f"(c.z), "+f"(c.w)
        : "r"(a0), "r"(a1), "r"(a2), "r"(a3), "r"(b0), "r"(b1));
}
__device__ __forceinline__ void cp16(unsigned d, const void* s){
    asm volatile("cp.async.cg.shared.global [%0], [%1], 16;\n" :: "r"(d), "l"(s));
}
__device__ __forceinline__ void cp_commit(){ asm volatile("cp.async.commit_group;\n"); }
__device__ __forceinline__ void cp_wait1(){ asm volatile("cp.async.wait_group 1;\n" ::: "memory"); }
__device__ __forceinline__ void cp_wait0(){ asm volatile("cp.async.wait_group 0;\n" ::: "memory"); }

// ---------------------------------------------------------------------------
__global__ __launch_bounds__(256)
void cvt_all(const float* __restrict__ x,  const float* __restrict__ Wq,
             const float* __restrict__ Wk, const float* __restrict__ Wv,
             const float* __restrict__ Wo)
{
    int i = blockIdx.x * 256 + threadIdx.x;   // float4 units
    const float* src; __half* dst; int off;
    if (i < 1048576) { src = x; dst = g_xh; off = i; }
    else {
        int j = i - 1048576;
        int seg = j >> 18;
        off = j & 262143;
        src = (seg == 0) ? Wq : (seg == 1) ? Wk : (seg == 2) ? Wv : Wo;
        dst = (seg == 3) ? g_Woh : g_Wqkvh + (size_t)seg * DM * DM;
    }
    float4 v = ((const float4*)src)[off];
    ((__half2*)dst)[2*off]   = __floats2half2_rn(v.x, v.y);
    ((__half2*)dst)[2*off+1] = __floats2half2_rn(v.z, v.w);
}

__global__ __launch_bounds__(256)
void concat_bias(const float* __restrict__ bq, const float* __restrict__ bk,
                 const float* __restrict__ bv)
{
    int i = blockIdx.x * 256 + threadIdx.x;
    float v = (i < 1024) ? bq[i] : (i < 2048 ? bk[i-1024] : bv[i-2048]);
    g_bqkv[i] = v;
}

// ---------------------------------------------------------------------------
// fp16 GEMM 128x128, BK=32.  omode 0: fp32 row-major; omode 3: fused QKV.
// ---------------------------------------------------------------------------
__global__ __launch_bounds__(256, 2)
void gemm_h(const __half* __restrict__ A, const __half* __restrict__ W,
            const float* __restrict__ bias, float* __restrict__ C,
            int N, int K, int omode)
{
    extern __shared__ __half smh[];
    __half* Asm = smh;                 // [3][128][40]
    __half* Bsm = smh + 3*128*40;
    const unsigned sA = (unsigned)__cvta_generic_to_shared(Asm);
    const unsigned sB = (unsigned)__cvta_generic_to_shared(Bsm);

    const int tid = threadIdx.x, lane = tid & 31, warp = tid >> 5;
    const int gid = lane >> 2, tig = lane & 3;
    const int wm = warp & 1, wn = warp >> 1;
    const int bm0 = blockIdx.y * 128, bn0 = blockIdx.x * 128;
    const int lr = tid >> 1, lkq = (tid & 1) * 16;
    const __half* Ag = A + (size_t)(bm0 + lr) * K + lkq;
    const __half* Wg = W + (size_t)(bn0 + lr) * K + lkq;
    const int NCH = K / 32;

    float4 acc[4][4];
    #pragma unroll
    for (int i = 0; i < 4; i++)
        #pragma unroll
        for (int j = 0; j < 4; j++) acc[i][j] = make_float4(0.f,0.f,0.f,0.f);

    auto issue = [&](int cc){
        int st = cc % 3, k0 = cc * 32;
        unsigned da = sA + (unsigned)(((st*128 + lr)*40 + lkq)*2);
        cp16(da,      Ag + k0);
        cp16(da + 16, Ag + k0 + 8);
        unsigned db = sB + (unsigned)(((st*128 + lr)*40 + lkq)*2);
        cp16(db,      Wg + k0);
        cp16(db + 16, Wg + k0 + 8);
        cp_commit();
    };

    issue(0); issue(1);

    for (int c = 0; c < NCH; c++) {
        if (c + 1 < NCH) cp_wait1(); else cp_wait0();
        __syncthreads();
        if (c + 2 < NCH) issue(c + 2);
        const __half* As_ = Asm + (c % 3)*128*40;
        const __half* Bs_ = Bsm + (c % 3)*128*40;
        #pragma unroll
        for (int ks = 0; ks < 2; ks++) {
            const int kb = ks * 16;
            unsigned af[4][4];
            #pragma unroll
            for (int mt = 0; mt < 4; mt++) {
                int m = wm*64 + mt*16 + gid;
                af[mt][0] = *(const unsigned*)&As_[m*40     + kb + 2*tig];
                af[mt][1] = *(const unsigned*)&As_[(m+8)*40 + kb + 2*tig];
                af[mt][2] = *(const unsigned*)&As_[m*40     + kb + 2*tig + 8];
                af[mt][3] = *(const unsigned*)&As_[(m+8)*40 + kb + 2*tig + 8];
            }
            #pragma unroll
            for (int nt = 0; nt < 4; nt++) {
                int n = wn*32 + nt*8 + gid;
                unsigned b0 = *(const unsigned*)&Bs_[n*40 + kb + 2*tig];
                unsigned b1 = *(const unsigned*)&Bs_[n*40 + kb + 2*tig + 8];
                #pragma unroll
                for (int mt = 0; mt < 4; mt++)
                    mma_f16(acc[mt][nt], af[mt][0],af[mt][1],af[mt][2],af[mt][3], b0, b1);
            }
        }
    }

    #pragma unroll
    for (int mt = 0; mt < 4; mt++) {
        int r0 = bm0 + wm*64 + mt*16 + gid;
        #pragma unroll
        for (int nt = 0; nt < 4; nt++) {
            int c0 = bn0 + wn*32 + nt*8 + tig*2;
            float bx, by;
            if (omode == 3) { bx = g_bqkv[c0]; by = g_bqkv[c0+1]; }
            else            { bx = bias[c0];   by = bias[c0+1];   }
            float2 lo = make_float2(acc[mt][nt].x + bx, acc[mt][nt].y + by);
            float2 hi = make_float2(acc[mt][nt].z + bx, acc[mt][nt].w + by);
            if (omode == 0) {
                float* p = C + (size_t)r0*N + c0;
                *(float2*)p = lo;
                *(float2*)(p + 8*(size_t)N) = hi;
            } else {
                int which = c0 >> 10;
                int e = c0 & 1023;
                int bb = r0 >> 11, tok = r0 & 2047, hh = e >> 6, hd = e & 63;
                size_t bh = (size_t)(bb*H + hh);
                if (which == 0) {
                    __half* p = g_Qh + (bh*NT + tok)*HD + hd;
                    *(__half2*)p          = __floats2half2_rn(lo.x, lo.y);
                    *(__half2*)(p + 8*HD) = __floats2half2_rn(hi.x, hi.y);
                } else if (which == 1) {
                    __half* p = g_Kh + (bh*NT + tok)*HD + hd;
                    *(__half2*)p          = __floats2half2_rn(lo.x, lo.y);
                    *(__half2*)(p + 8*HD) = __floats2half2_rn(hi.x, hi.y);
                } else {
                    __half* p = g_Vh + (bh*HD + hd)*NT + tok;
                    p[0]      = __float2half_rn(lo.x);
                    p[NT]     = __float2half_rn(lo.y);
                    p[8]      = __float2half_rn(hi.x);
                    p[NT + 8] = __float2half_rn(hi.y);
                }
            }
        }
    }
}

// ---------------------------------------------------------------------------
// Fused scores + exp + row Z/T/Zi.  fp16 mma; BK=32.
// ---------------------------------------------------------------------------
__global__ __launch_bounds__(256, 2)
void scores_exp_mma(const float* __restrict__ pbs, const int* __restrict__ perm)
{
    extern __shared__ char smraw[];
    float* pfi = (float*)smraw;
    float* pfj = pfi + 128;
    __half* Qs = (__half*)(smraw + 1024);          // [128][72]
    __half* Ks = Qs + 128*72;                      // [3][128][40]
    const unsigned sK = (unsigned)__cvta_generic_to_shared(Ks);

    const int tid = threadIdx.x, lane = tid & 31, warp = tid >> 5;
    const int gid = lane >> 2, tig = lane & 3;
    const int wm = warp & 1, wn = warp >> 1;
    const int bh = blockIdx.y, b = bh >> 4, h = bh & 15;
    const int bi0 = blockIdx.x * 128;
    const float pb = fabsf(pbs[h]);

    const __half* Qg = g_Qh + ((size_t)bh*NT + bi0)*HD;
    const __half* Kbase = g_Kh + (size_t)bh*NT*HD;
    const int lr = tid >> 1;
    const int lq8 = (tid & 1) * 8;
    const int lk16 = (tid & 1) * 16;

    #pragma unroll
    for (int cq = 0; cq < 4; cq++) {
        int kk = lq8 + cq*16;
        uint4 q = *(const uint4*)(Qg + (size_t)lr*HD + kk);
        *(uint4*)&Qs[lr*72 + kk] = q;
    }
    if (tid < 128) pfi[tid] = (float)perm[b*NT + bi0 + tid];

    float Zr[8] = {0,0,0,0,0,0,0,0};
    float Tr[8] = {0,0,0,0,0,0,0,0};

    auto issue = [&](int cc){
        int st = cc % 3, jt = cc >> 1, kc = (cc & 1) * 32;
        unsigned d = sK + (unsigned)(((st*128 + lr)*40 + lk16)*2);
        const __half* s = Kbase + (size_t)(jt*128 + lr)*HD + kc + lk16;
        cp16(d, s); cp16(d + 16, s + 8);
        cp_commit();
    };

    issue(0); issue(1);
    const int NCH = 32;

    for (int jt = 0; jt < 16; jt++) {
        const int j0 = jt * 128;
        float4 acc[4][4];
        #pragma unroll
        for (int i = 0; i < 4; i++)
            #pragma unroll
            for (int j = 0; j < 4; j++) acc[i][j] = make_float4(0.f,0.f,0.f,0.f);

        #pragma unroll
        for (int k2 = 0; k2 < 2; k2++) {
            const int c = jt*2 + k2;
            if (c + 1 < NCH) cp_wait1(); else cp_wait0();
            __syncthreads();
            if (c + 2 < NCH) issue(c + 2);
            if (k2 == 0 && tid < 128) pfj[tid] = (float)perm[b*NT + j0 + tid];
            const __half* Ks_ = Ks + (c % 3)*128*40;
            const int kc = k2 * 32;

            #pragma unroll
            for (int ks = 0; ks < 2; ks++) {
                const int kb = ks * 16;
                unsigned af[4][4];
                #pragma unroll
                for (int mt = 0; mt < 4; mt++) {
                    int m = wm*64 + mt*16 + gid;
                    af[mt][0] = *(const unsigned*)&Qs[m*72     + kc + kb + 2*tig];
                    af[mt][1] = *(const unsigned*)&Qs[(m+8)*72 + kc + kb + 2*tig];
                    af[mt][2] = *(const unsigned*)&Qs[m*72     + kc + kb + 2*tig + 8];
                    af[mt][3] = *(const unsigned*)&Qs[(m+8)*72 + kc + kb + 2*tig + 8];
                }
                #pragma unroll
                for (int nt = 0; nt < 4; nt++) {
                    int n = wn*32 + nt*8 + gid;
                    unsigned b0 = *(const unsigned*)&Ks_[n*40 + kb + 2*tig];
                    unsigned b1 = *(const unsigned*)&Ks_[n*40 + kb + 2*tig + 8];
                    #pragma unroll
                    for (int mt = 0; mt < 4; mt++)
                        mma_f16(acc[mt][nt], af[mt][0],af[mt][1],af[mt][2],af[mt][3], b0, b1);
                }
            }
        }

        #pragma unroll
        for (int mt = 0; mt < 4; mt++) {
            int rl = wm*64 + mt*16 + gid;
            float pa = pfi[rl], pc = pfi[rl+8];
            #pragma unroll
            for (int nt = 0; nt < 4; nt++) {
                int cl = wn*32 + nt*8 + tig*2;
                float d0 = pfj[cl], d1 = pfj[cl+1];
                float4 a = acc[mt][nt];
                float s00 = a.x*0.125f - fabsf(pa - d0)*pb;
                float s01 = a.y*0.125f - fabsf(pa - d1)*pb;
                float s10 = a.z*0.125f - fabsf(pc - d0)*pb;
                float s11 = a.w*0.125f - fabsf(pc - d1)*pb;
                __half2 hA = __floats2half2_rn(__expf(s00), __expf(s01));
                __half2 hB = __floats2half2_rn(__expf(s10), __expf(s11));
                float2 fA = __half22float2(hA);
                float2 fB = __half22float2(hB);
                Zr[mt*2]   += fA.x + fA.y;  Tr[mt*2]   += s00*fA.x + s01*fA.y;
                Zr[mt*2+1] += fB.x + fB.y;  Tr[mt*2+1] += s10*fB.x + s11*fB.y;
                size_t base = ((size_t)bh*NT + bi0 + rl)*NT + j0 + cl;
                *(__half2*)(g_Eh + base)        = hA;
                *(__half2*)(g_Eh + base + 8*NT) = hB;
            }
        }
    }

    float* redZ = (float*)Qs;
    float* redT = redZ + 2048;
    const int pcol = wn*4 + tig;
    __syncthreads();
    #pragma unroll
    for (int mt = 0; mt < 4; mt++) {
        int r0 = wm*64 + mt*16 + gid;
        redZ[pcol*128 + r0]     = Zr[mt*2];
        redZ[pcol*128 + r0 + 8] = Zr[mt*2+1];
        redT[pcol*128 + r0]     = Tr[mt*2];
        redT[pcol*128 + r0 + 8] = Tr[mt*2+1];
    }
    __syncthreads();
    if (tid < 128) {
        float sz = 0.f, st = 0.f;
        #pragma unroll
        for (int t = 0; t < 16; t++) { sz += redZ[t*128 + tid]; st += redT[t*128 + tid]; }
        g_Z[(size_t)bh*NT + bi0 + tid]  = sz;
        g_Zi[(size_t)bh*NT + bi0 + tid] = 1.0f / sz;
        g_T[(size_t)bh*NT + bi0 + tid]  = st;
    }
}

// ---------------------------------------------------------------------------
// ctx(half) = (E @ V) / Z.  fp16 mma; BK=32.
// ---------------------------------------------------------------------------
__global__ __launch_bounds__(256, 2)
void av_mma()
{
    __shared__ __half Es[3][128][40];
    __shared__ __half Vs[3][64][40];
    __shared__ float zin[128];
    const unsigned sE = (unsigned)__cvta_generic_to_shared(&Es[0][0][0]);
    const unsigned sV = (unsigned)__cvta_generic_to_shared(&Vs[0][0][0]);

    const int tid = threadIdx.x, lane = tid & 31, warp = tid >> 5;
    const int gid = lane >> 2, tig = lane & 3;
    const int wm = warp >> 1, wn = warp & 1;
    const int bh = blockIdx.y, b = bh >> 4, h = bh & 15;
    const int bi0 = blockIdx.x * 128;

    const int lr = tid >> 1, lk16 = (tid & 1) * 16;
    const __half* Eg = g_Eh + ((size_t)bh*NT + bi0 + lr)*NT + lk16;
    const __half* Vg = g_Vh + (size_t)bh*HD*NT;
    const int vr = (tid & 127) >> 1;

    if (tid < 128) zin[tid] = g_Zi[(size_t)bh*NT + bi0 + tid];

    float4 acc[2][4];
    #pragma unroll
    for (int i = 0; i < 2; i++)
        #pragma unroll
        for (int j = 0; j < 4; j++) acc[i][j] = make_float4(0.f,0.f,0.f,0.f);

    auto issue = [&](int cc){
        int st = cc % 3, k0 = cc * 32;
        unsigned dE = sE + (unsigned)(((st*128 + lr)*40 + lk16)*2);
        cp16(dE,      Eg + k0);
        cp16(dE + 16, Eg + k0 + 8);
        if (tid < 128) {
            unsigned dV = sV + (unsigned)(((st*64 + vr)*40 + lk16)*2);
            const __half* s = Vg + (size_t)vr*NT + k0 + lk16;
            cp16(dV, s); cp16(dV + 16, s + 8);
        }
        cp_commit();
    };

    issue(0); issue(1);
    const int NCH = NT / 32;   // 64

    for (int c = 0; c < NCH; c++) {
        if (c + 1 < NCH) cp_wait1(); else cp_wait0();
        __syncthreads();
        if (c + 2 < NCH) issue(c + 2);
        const __half* Es_ = &Es[c % 3][0][0];
        const __half* Vs_ = &Vs[c % 3][0][0];

        #pragma unroll
        for (int ks = 0; ks < 2; ks++) {
            const int kb = ks * 16;
            unsigned af[2][4];
            #pragma unroll
            for (int mt = 0; mt < 2; mt++) {
                int m = wm*32 + mt*16 + gid;
                af[mt][0] = *(const unsigned*)&Es_[m*40     + kb + 2*tig];
                af[mt][1] = *(const unsigned*)&Es_[(m+8)*40 + kb + 2*tig];
                af[mt][2] = *(const unsigned*)&Es_[m*40     + kb + 2*tig + 8];
                af[mt][3] = *(const unsigned*)&Es_[(m+8)*40 + kb + 2*tig + 8];
            }
            #pragma unroll
            for (int nt = 0; nt < 4; nt++) {
                int n = wn*32 + nt*8 + gid;
                unsigned b0 = *(const unsigned*)&Vs_[n*40 + kb + 2*tig];
                unsigned b1 = *(const unsigned*)&Vs_[n*40 + kb + 2*tig + 8];
                #pragma unroll
                for (int mt = 0; mt < 2; mt++)
                    mma_f16(acc[mt][nt], af[mt][0],af[mt][1],af[mt][2],af[mt][3], b0, b1);
            }
        }
    }

    #pragma unroll
    for (int mt = 0; mt < 2; mt++) {
        int rl = wm*32 + mt*16 + gid;
        float z0 = zin[rl], z1 = zin[rl+8];
        #pragma unroll
        for (int nt = 0; nt < 4; nt++) {
            int cl = wn*32 + nt*8 + tig*2;
            float4 a = acc[mt][nt];
            size_t base = ((size_t)b*NT + bi0 + rl)*DM + h*HD + cl;
            *(__half2*)(g_ctxh + base)        = __floats2half2_rn(a.x*z0, a.y*z0);
            *(__half2*)(g_ctxh + base + 8*DM) = __floats2half2_rn(a.z*z1, a.w*z1);
        }
    }
}

// ---------------------------------------------------------------------------
__global__ __launch_bounds__(256)
void build_P_kernel()
{
    size_t idx8 = ((size_t)blockIdx.x * 256 + threadIdx.x) * 8;
    size_t b = idx8 / ((size_t)NT*NT);
    size_t rem = idx8 - b * (size_t)NT*NT;
    int i = (int)(rem >> 11);
    float s[8] = {0,0,0,0,0,0,0,0};
    #pragma unroll
    for (int h = 0; h < H; h++) {
        const uint4* src = (const uint4*)&g_Eh[(size_t)(b*H + h)*NT*NT + rem];
        uint4 raw = __ldcg(src);
        float zi = g_Zi[(size_t)(b*H + h)*NT + i];
        float2 p0 = __half22float2(*(__half2*)&raw.x);
        float2 p1 = __half22float2(*(__half2*)&raw.y);
        float2 p2 = __half22float2(*(__half2*)&raw.z);
        float2 p3 = __half22float2(*(__half2*)&raw.w);
        s[0] += p0.x*zi; s[1] += p0.y*zi; s[2] += p1.x*zi; s[3] += p1.y*zi;
        s[4] += p2.x*zi; s[5] += p2.y*zi; s[6] += p3.x*zi; s[7] += p3.y*zi;
    }
    float o[8];
    #pragma unroll
    for (int k = 0; k < 8; k++)
        o[k] = expf(logf(s[k] * (1.0f/16.0f) + EPSF) * 10.0f);
    *(float4*)&g_P[idx8]     = make_float4(o[0],o[1],o[2],o[3]);
    *(float4*)&g_P[idx8 + 4] = make_float4(o[4],o[5],o[6],o[7]);
}

// ---------------------------------------------------------------------------
__device__ __forceinline__ void grid_sync(unsigned &gen)
{
    __syncthreads();
    if (threadIdx.x == 0) {
        gen++;
        __threadfence();
        unsigned old = atomicAdd(&g_barcount, 1);
        if (old == NB_SINK - 1) {
            atomicExch(&g_barcount, 0);
            atomicExch(&g_bargen, gen);
        } else {
            while (*(volatile unsigned*)&g_bargen < gen) __nanosleep(64);
        }
    }
    __syncthreads();
}

__global__ __launch_bounds__(256)
void sinkhorn_persist(const int* __restrict__ perm, float* __restrict__ outp)
{
    __shared__ float sv[NT];
    __shared__ float su[16];
    __shared__ float red[256];
    const int tid = threadIdx.x, bk = blockIdx.x;
    const int lane = tid & 31, w = tid >> 5;
    unsigned gen = *(volatile unsigned*)&g_bargen;

    const int row0 = bk * 16;
    const int bb = row0 >> 11;
    const int blkb = bk & 127;
    const int jbase = blkb * 16;
    float* cp = g_colpart + ((size_t)bb*128 + blkb)*NT;

    if (tid < 16) {
        su[tid] = 1.0f;
        __stcg(&g_v[bb*NT + jbase + tid], 1.0f);
    }
    grid_sync(gen);

    for (int it = 0; it < 10; it++) {
        for (int j = tid; j < NT; j += 256) sv[j] = __ldcg(&g_v[bb*NT + j]);
        __syncthreads();
        #pragma unroll
        for (int rr = 0; rr < 2; rr++) {
            int rl = w*2 + rr;
            const float* Pr = g_P + (size_t)(row0 + rl)*NT;
            float s = 0.f;
            #pragma unroll 8
            for (int j = lane; j < NT; j += 32) s += Pr[j] * sv[j];
            #pragma unroll
            for (int o = 16; o > 0; o >>= 1) s += __shfl_xor_sync(0xffffffffu, s, o);
            if (lane == 0) { float u = su[rl]; su[rl] = u / (u * s + EPSF); }
        }
        __syncthreads();
        float pa[8] = {0,0,0,0,0,0,0,0};
        #pragma unroll
        for (int i = 0; i < 16; i++) {
            float ui = su[i];
            const float* Pr = g_P + (size_t)(row0 + i)*NT;
            #pragma unroll
            for (int k = 0; k < 8; k++) pa[k] += ui * Pr[tid + k*256];
        }
        #pragma unroll
        for (int k = 0; k < 8; k++) cp[tid + k*256] = pa[k];
        grid_sync(gen);
        {
            int c = tid & 15, grp = tid >> 4;
            const float* base = g_colpart + (size_t)bb*128*NT + jbase + c;
            float s = 0.f;
            #pragma unroll
            for (int kk = 0; kk < 8; kk++)
                s += __ldcg(&base[(size_t)(grp*8 + kk)*NT]);
            red[tid] = s; __syncthreads();
            if (tid < 128) red[tid] += red[tid+128];
            __syncthreads();
            if (tid < 64)  red[tid] += red[tid+64];
            __syncthreads();
            if (tid < 32)  red[tid] += red[tid+32];
            __syncthreads();
            if (tid < 16) {
                float tot = red[tid] + red[tid+16];
                int jj = bb*NT + jbase + tid;
                float v = __ldcg(&g_v[jj]);
                __stcg(&g_v[jj], v / (v * tot + EPSF));
            }
        }
        grid_sync(gen);
    }

    for (int j = tid; j < NT; j += 256) sv[j] = __ldcg(&g_v[bb*NT + j]);
    __syncthreads();
    #pragma unroll
    for (int rr = 0; rr < 2; rr++) {
        int r = row0 + w*2 + rr;
        const float* Pr = g_P + (size_t)r * NT;
        float best = -INFINITY; int bj = NT;
        for (int j = lane; j < NT; j += 32) {
            float val = Pr[j] * sv[j];
            if (val > best) { best = val; bj = j; }
        }
        #pragma unroll
        for (int o = 16; o > 0; o >>= 1) {
            float ob = __shfl_xor_sync(0xffffffffu, best, o);
            int   oj = __shfl_xor_sync(0xffffffffu, bj, o);
            if (ob > best || (ob == best && oj < bj)) { best = ob; bj = oj; }
        }
        if (lane == 0) outp[r] = (float)perm[bb*NT + bj];
    }
}

// ---------------------------------------------------------------------------
__global__ __launch_bounds__(256)
void cert_kernel(const float* __restrict__ cert, const float* __restrict__ ctemp,
                 float* __restrict__ out)
{
    const int idx = blockIdx.x * 256 + threadIdx.x;
    const int b = idx >> 11, i = idx & 2047;
    float s = 0.f;
    #pragma unroll
    for (int h = 0; h < H; h++) {
        size_t o = (size_t)(b*H + h)*NT + i;
        float Z = g_Z[o];
        s += logf(Z) - g_T[o] / Z;
    }
    float ent = s * (1.0f / 16.0f);
    float z = ctemp[0] * (logf(2048.0f) - ent);
    out[idx] = fmaxf(cert[idx], 1.0f / (1.0f + expf(-z)));
}

extern "C" void kernel_launch(void* const* d_in, const int* in_sizes, int n_in,
                              void* d_out, int out_size)
{
    const float* x     = (const float*)d_in[0];
    const float* cert  = (const float*)d_in[1];
    const int*   perm  = (const int*)  d_in[2];
    const float* Wq    = (const float*)d_in[3];
    const float* bq    = (const float*)d_in[4];
    const float* Wk    = (const float*)d_in[5];
    const float* bk    = (const float*)d_in[6];
    const float* Wv    = (const float*)d_in[7];
    const float* bvv   = (const float*)d_in[8];
    const float* Wo    = (const float*)d_in[9];
    const float* bo    = (const float*)d_in[10];
    const float* pbs   = (const float*)d_in[11];
    const float* ctemp = (const float*)d_in[12];
    float* out = (float*)d_out;

    __half *pxh, *pWqkv, *pWoh, *pCtx;
    cudaGetSymbolAddress((void**)&pxh,   g_xh);
    cudaGetSymbolAddress((void**)&pWqkv, g_Wqkvh);
    cudaGetSymbolAddress((void**)&pWoh,  g_Woh);
    cudaGetSymbolAddress((void**)&pCtx,  g_ctxh);

    const int SMEM_H = 2*3*128*40*2;                 // 61440 B
    const int SMEM_S = 1024 + 128*72*2 + 3*128*40*2; // 50176 B
    cudaFuncSetAttribute(gemm_h, cudaFuncAttributeMaxDynamicSharedMemorySize, SMEM_H);
    cudaFuncSetAttribute(scores_exp_mma, cudaFuncAttributeMaxDynamicSharedMemorySize, SMEM_S);

    const int M = B * NT;                  // 4096

    // fork/join resources (created once; reused across calls; never destroyed)
    static cudaStream_t s2 = nullptr;
    static cudaEvent_t evFork = nullptr, evJoin = nullptr;
    if (s2 == nullptr) {
        cudaStreamCreateWithFlags(&s2, cudaStreamNonBlocking);
        cudaEventCreateWithFlags(&evFork, cudaEventDisableTiming);
        cudaEventCreateWithFlags(&evJoin, cudaEventDisableTiming);
    }

    // main stream: prep + QKV + scores
    cvt_all<<<8192, 256>>>(x, Wq, Wk, Wv, Wo);
    concat_bias<<<12, 256>>>(bq, bk, bvv);

    dim3 gQKV(3*DM/128, M/128);
    gemm_h<<<gQKV, 256, SMEM_H>>>(pxh, pWqkv, nullptr, nullptr, 3*DM, DM, 3);

    dim3 gS(NT/128, B*H);
    scores_exp_mma<<<gS, 256, SMEM_S>>>(pbs, perm);

    // fork: branch B (build_P -> sinkhorn, cert) on s2
    cudaEventRecord(evFork, 0);
    cudaStreamWaitEvent(s2, evFork, 0);
    build_P_kernel<<<4096, 256, 0, s2>>>();
    cert_kernel<<<(B*NT)/256, 256, 0, s2>>>(cert, ctemp, out + (size_t)M*DM);
    sinkhorn_persist<<<NB_SINK, 256, 0, s2>>>(perm, out + (size_t)M*DM + B*NT);
    cudaEventRecord(evJoin, s2);

    // branch A (av -> out projection) on main stream
    av_mma<<<gS, 256>>>();
    dim3 gO(DM/128, M/128);
    gemm_h<<<gO, 256, SMEM_H>>>(pCtx, pWoh, bo, out, DM, DM, 0);

    // join
    cudaStreamWaitEvent(0, evJoin, 0);
}

// round 14
// speedup vs baseline: 1.8722x; 1.0724x over previous
#include <cuda_runtime.h>
#include <cuda_fp16.h>
#include <math.h>

#define B   2
#define NT  2048
#define DM  1024
#define H   16
#define HD  64
#define EPSF 1e-10f
#define NB_SINK 256

__device__ __half g_xh[(size_t)B*NT*DM];
__device__ __half g_Wqkvh[(size_t)3*DM*DM];
__device__ __half g_Woh[(size_t)DM*DM];
__device__ float  g_bqkv[3*DM];
__device__ __half g_Qh[(size_t)B*H*NT*HD];          // [bh][tok][hd], pre-scaled by 1/8
__device__ __half g_Kh[(size_t)B*H*NT*HD];          // [bh][tok][hd]
__device__ __half g_Vh[(size_t)B*H*NT*HD];          // [bh][hd][tok]
__device__ __half g_Eh[(size_t)B*H*NT*NT];          // exp(scores), fp16
__device__ __half g_ctxh[(size_t)B*NT*DM];
__device__ float g_P[(size_t)B*NT*NT];
__device__ float g_Z[(size_t)B*H*NT];
__device__ float g_T[(size_t)B*H*NT];
__device__ float g_Zi[(size_t)B*H*NT];
__device__ float g_u[B*NT];
__device__ float g_v[B*NT];
__device__ float g_colpart[(size_t)B*128*NT];
__device__ unsigned g_barcount = 0;
__device__ unsigned g_bargen = 0;

__device__ __forceinline__ void mma_f16(float4 &c,
    unsigned a0, unsigned a1, unsigned a2, unsigned a3,
    unsigned b0, unsigned b1)
{
    asm("mma.sync.aligned.m16n8k16.row.col.f32.f16.f16.f32 "
        "{%0,%1,%2,%3},{%4,%5,%6,%7},{%8,%9},{%0,%1,%2,%3};"
        : "+f"(c.x), "+f"(c.y), "+f"(c.z), "+f"(c.w)
        : "r"(a0), "r"(a1), "r"(a2), "r"(a3), "r"(b0), "r"(b1));
}
__device__ __forceinline__ void cp16(unsigned d, const void* s){
    asm volatile("cp.async.cg.shared.global [%0], [%1], 16;\n" :: "r"(d), "l"(s));
}
__device__ __forceinline__ void cp_commit(){ asm volatile("cp.async.commit_group;\n"); }
__device__ __forceinline__ void cp_wait1(){ asm volatile("cp.async.wait_group 1;\n" ::: "memory"); }
__device__ __forceinline__ void cp_wait0(){ asm volatile("cp.async.wait_group 0;\n" ::: "memory"); }

// ---------------------------------------------------------------------------
__global__ __launch_bounds__(256)
void cvt_all(const float* __restrict__ x,  const float* __restrict__ Wq,
             const float* __restrict__ Wk, const float* __restrict__ Wv,
             const float* __restrict__ Wo)
{
    int i = blockIdx.x * 256 + threadIdx.x;   // float4 units
    const float* src; __half* dst; int off;
    if (i < 1048576) { src = x; dst = g_xh; off = i; }
    else {
        int j = i - 1048576;
        int seg = j >> 18;
        off = j & 262143;
        src = (seg == 0) ? Wq : (seg == 1) ? Wk : (seg == 2) ? Wv : Wo;
        dst = (seg == 3) ? g_Woh : g_Wqkvh + (size_t)seg * DM * DM;
    }
    float4 v = ((const float4*)src)[off];
    ((__half2*)dst)[2*off]   = __floats2half2_rn(v.x, v.y);
    ((__half2*)dst)[2*off+1] = __floats2half2_rn(v.z, v.w);
}

__global__ __launch_bounds__(256)
void concat_bias(const float* __restrict__ bq, const float* __restrict__ bk,
                 const float* __restrict__ bv)
{
    int i = blockIdx.x * 256 + threadIdx.x;
    float v = (i < 1024) ? bq[i] : (i < 2048 ? bk[i-1024] : bv[i-2048]);
    g_bqkv[i] = v;
}

// ---------------------------------------------------------------------------
// fp16 GEMM 128x128, BK=32.  omode 0: fp32 row-major; omode 3: fused QKV
// (Q written pre-scaled by 1/8).
// ---------------------------------------------------------------------------
__global__ __launch_bounds__(256, 2)
void gemm_h(const __half* __restrict__ A, const __half* __restrict__ W,
            const float* __restrict__ bias, float* __restrict__ C,
            int N, int K, int omode)
{
    extern __shared__ __half smh[];
    __half* Asm = smh;                 // [3][128][40]
    __half* Bsm = smh + 3*128*40;
    const unsigned sA = (unsigned)__cvta_generic_to_shared(Asm);
    const unsigned sB = (unsigned)__cvta_generic_to_shared(Bsm);

    const int tid = threadIdx.x, lane = tid & 31, warp = tid >> 5;
    const int gid = lane >> 2, tig = lane & 3;
    const int wm = warp & 1, wn = warp >> 1;
    const int bm0 = blockIdx.y * 128, bn0 = blockIdx.x * 128;
    const int lr = tid >> 1, lkq = (tid & 1) * 16;
    const __half* Ag = A + (size_t)(bm0 + lr) * K + lkq;
    const __half* Wg = W + (size_t)(bn0 + lr) * K + lkq;
    const int NCH = K / 32;

    float4 acc[4][4];
    #pragma unroll
    for (int i = 0; i < 4; i++)
        #pragma unroll
        for (int j = 0; j < 4; j++) acc[i][j] = make_float4(0.f,0.f,0.f,0.f);

    auto issue = [&](int cc){
        int st = cc % 3, k0 = cc * 32;
        unsigned da = sA + (unsigned)(((st*128 + lr)*40 + lkq)*2);
        cp16(da,      Ag + k0);
        cp16(da + 16, Ag + k0 + 8);
        unsigned db = sB + (unsigned)(((st*128 + lr)*40 + lkq)*2);
        cp16(db,      Wg + k0);
        cp16(db + 16, Wg + k0 + 8);
        cp_commit();
    };

    issue(0); issue(1);

    for (int c = 0; c < NCH; c++) {
        if (c + 1 < NCH) cp_wait1(); else cp_wait0();
        __syncthreads();
        if (c + 2 < NCH) issue(c + 2);
        const __half* As_ = Asm + (c % 3)*128*40;
        const __half* Bs_ = Bsm + (c % 3)*128*40;
        #pragma unroll
        for (int ks = 0; ks < 2; ks++) {
            const int kb = ks * 16;
            unsigned af[4][4];
            #pragma unroll
            for (int mt = 0; mt < 4; mt++) {
                int m = wm*64 + mt*16 + gid;
                af[mt][0] = *(const unsigned*)&As_[m*40     + kb + 2*tig];
                af[mt][1] = *(const unsigned*)&As_[(m+8)*40 + kb + 2*tig];
                af[mt][2] = *(const unsigned*)&As_[m*40     + kb + 2*tig + 8];
                af[mt][3] = *(const unsigned*)&As_[(m+8)*40 + kb + 2*tig + 8];
            }
            #pragma unroll
            for (int nt = 0; nt < 4; nt++) {
                int n = wn*32 + nt*8 + gid;
                unsigned b0 = *(const unsigned*)&Bs_[n*40 + kb + 2*tig];
                unsigned b1 = *(const unsigned*)&Bs_[n*40 + kb + 2*tig + 8];
                #pragma unroll
                for (int mt = 0; mt < 4; mt++)
                    mma_f16(acc[mt][nt], af[mt][0],af[mt][1],af[mt][2],af[mt][3], b0, b1);
            }
        }
    }

    #pragma unroll
    for (int mt = 0; mt < 4; mt++) {
        int r0 = bm0 + wm*64 + mt*16 + gid;
        #pragma unroll
        for (int nt = 0; nt < 4; nt++) {
            int c0 = bn0 + wn*32 + nt*8 + tig*2;
            float bx, by;
            if (omode == 3) { bx = g_bqkv[c0]; by = g_bqkv[c0+1]; }
            else            { bx = bias[c0];   by = bias[c0+1];   }
            float2 lo = make_float2(acc[mt][nt].x + bx, acc[mt][nt].y + by);
            float2 hi = make_float2(acc[mt][nt].z + bx, acc[mt][nt].w + by);
            if (omode == 0) {
                float* p = C + (size_t)r0*N + c0;
                *(float2*)p = lo;
                *(float2*)(p + 8*(size_t)N) = hi;
            } else {
                int which = c0 >> 10;
                int e = c0 & 1023;
                int bb = r0 >> 11, tok = r0 & 2047, hh = e >> 6, hd = e & 63;
                size_t bh = (size_t)(bb*H + hh);
                if (which == 0) {
                    // pre-scale Q by 1/8 (score scale folded in)
                    __half* p = g_Qh + (bh*NT + tok)*HD + hd;
                    *(__half2*)p          = __floats2half2_rn(lo.x*0.125f, lo.y*0.125f);
                    *(__half2*)(p + 8*HD) = __floats2half2_rn(hi.x*0.125f, hi.y*0.125f);
                } else if (which == 1) {
                    __half* p = g_Kh + (bh*NT + tok)*HD + hd;
                    *(__half2*)p          = __floats2half2_rn(lo.x, lo.y);
                    *(__half2*)(p + 8*HD) = __floats2half2_rn(hi.x, hi.y);
                } else {
                    __half* p = g_Vh + (bh*HD + hd)*NT + tok;
                    p[0]      = __float2half_rn(lo.x);
                    p[NT]     = __float2half_rn(lo.y);
                    p[8]      = __float2half_rn(hi.x);
                    p[NT + 8] = __float2half_rn(hi.y);
                }
            }
        }
    }
}

// ---------------------------------------------------------------------------
// Fused scores + exp + row Z/T/Zi.  Q pre-scaled; pb folded into pfi/pfj.
// ---------------------------------------------------------------------------
__global__ __launch_bounds__(256, 2)
void scores_exp_mma(const float* __restrict__ pbs, const int* __restrict__ perm)
{
    extern __shared__ char smraw[];
    float* pfi = (float*)smraw;
    float* pfj = pfi + 128;
    __half* Qs = (__half*)(smraw + 1024);          // [128][72]
    __half* Ks = Qs + 128*72;                      // [3][128][40]
    const unsigned sK = (unsigned)__cvta_generic_to_shared(Ks);

    const int tid = threadIdx.x, lane = tid & 31, warp = tid >> 5;
    const int gid = lane >> 2, tig = lane & 3;
    const int wm = warp & 1, wn = warp >> 1;
    const int bh = blockIdx.y, b = bh >> 4, h = bh & 15;
    const int bi0 = blockIdx.x * 128;
    const float pb = fabsf(pbs[h]);

    const __half* Qg = g_Qh + ((size_t)bh*NT + bi0)*HD;
    const __half* Kbase = g_Kh + (size_t)bh*NT*HD;
    const int lr = tid >> 1;
    const int lq8 = (tid & 1) * 8;
    const int lk16 = (tid & 1) * 16;

    #pragma unroll
    for (int cq = 0; cq < 4; cq++) {
        int kk = lq8 + cq*16;
        uint4 q = *(const uint4*)(Qg + (size_t)lr*HD + kk);
        *(uint4*)&Qs[lr*72 + kk] = q;
    }
    if (tid < 128) pfi[tid] = (float)perm[b*NT + bi0 + tid] * pb;

    float Zr[8] = {0,0,0,0,0,0,0,0};
    float Tr[8] = {0,0,0,0,0,0,0,0};

    auto issue = [&](int cc){
        int st = cc % 3, jt = cc >> 1, kc = (cc & 1) * 32;
        unsigned d = sK + (unsigned)(((st*128 + lr)*40 + lk16)*2);
        const __half* s = Kbase + (size_t)(jt*128 + lr)*HD + kc + lk16;
        cp16(d, s); cp16(d + 16, s + 8);
        cp_commit();
    };

    issue(0); issue(1);
    const int NCH = 32;

    for (int jt = 0; jt < 16; jt++) {
        const int j0 = jt * 128;
        float4 acc[4][4];
        #pragma unroll
        for (int i = 0; i < 4; i++)
            #pragma unroll
            for (int j = 0; j < 4; j++) acc[i][j] = make_float4(0.f,0.f,0.f,0.f);

        #pragma unroll
        for (int k2 = 0; k2 < 2; k2++) {
            const int c = jt*2 + k2;
            if (c + 1 < NCH) cp_wait1(); else cp_wait0();
            __syncthreads();
            if (c + 2 < NCH) issue(c + 2);
            if (k2 == 0 && tid < 128) pfj[tid] = (float)perm[b*NT + j0 + tid] * pb;
            const __half* Ks_ = Ks + (c % 3)*128*40;
            const int kc = k2 * 32;

            #pragma unroll
            for (int ks = 0; ks < 2; ks++) {
                const int kb = ks * 16;
                unsigned af[4][4];
                #pragma unroll
                for (int mt = 0; mt < 4; mt++) {
                    int m = wm*64 + mt*16 + gid;
                    af[mt][0] = *(const unsigned*)&Qs[m*72     + kc + kb + 2*tig];
                    af[mt][1] = *(const unsigned*)&Qs[(m+8)*72 + kc + kb + 2*tig];
                    af[mt][2] = *(const unsigned*)&Qs[m*72     + kc + kb + 2*tig + 8];
                    af[mt][3] = *(const unsigned*)&Qs[(m+8)*72 + kc + kb + 2*tig + 8];
                }
                #pragma unroll
                for (int nt = 0; nt < 4; nt++) {
                    int n = wn*32 + nt*8 + gid;
                    unsigned b0 = *(const unsigned*)&Ks_[n*40 + kb + 2*tig];
                    unsigned b1 = *(const unsigned*)&Ks_[n*40 + kb + 2*tig + 8];
                    #pragma unroll
                    for (int mt = 0; mt < 4; mt++)
                        mma_f16(acc[mt][nt], af[mt][0],af[mt][1],af[mt][2],af[mt][3], b0, b1);
                }
            }
        }

        #pragma unroll
        for (int mt = 0; mt < 4; mt++) {
            int rl = wm*64 + mt*16 + gid;
            float pa = pfi[rl], pc = pfi[rl+8];
            #pragma unroll
            for (int nt = 0; nt < 4; nt++) {
                int cl = wn*32 + nt*8 + tig*2;
                float d0 = pfj[cl], d1 = pfj[cl+1];
                float4 a = acc[mt][nt];
                float s00 = a.x - fabsf(pa - d0);
                float s01 = a.y - fabsf(pa - d1);
                float s10 = a.z - fabsf(pc - d0);
                float s11 = a.w - fabsf(pc - d1);
                __half2 hA = __floats2half2_rn(__expf(s00), __expf(s01));
                __half2 hB = __floats2half2_rn(__expf(s10), __expf(s11));
                float2 fA = __half22float2(hA);
                float2 fB = __half22float2(hB);
                Zr[mt*2]   += fA.x + fA.y;  Tr[mt*2]   += s00*fA.x + s01*fA.y;
                Zr[mt*2+1] += fB.x + fB.y;  Tr[mt*2+1] += s10*fB.x + s11*fB.y;
                size_t base = ((size_t)bh*NT + bi0 + rl)*NT + j0 + cl;
                *(__half2*)(g_Eh + base)        = hA;
                *(__half2*)(g_Eh + base + 8*NT) = hB;
            }
        }
    }

    float* redZ = (float*)Qs;
    float* redT = redZ + 2048;
    const int pcol = wn*4 + tig;
    __syncthreads();
    #pragma unroll
    for (int mt = 0; mt < 4; mt++) {
        int r0 = wm*64 + mt*16 + gid;
        redZ[pcol*128 + r0]     = Zr[mt*2];
        redZ[pcol*128 + r0 + 8] = Zr[mt*2+1];
        redT[pcol*128 + r0]     = Tr[mt*2];
        redT[pcol*128 + r0 + 8] = Tr[mt*2+1];
    }
    __syncthreads();
    if (tid < 128) {
        float sz = 0.f, st = 0.f;
        #pragma unroll
        for (int t = 0; t < 16; t++) { sz += redZ[t*128 + tid]; st += redT[t*128 + tid]; }
        g_Z[(size_t)bh*NT + bi0 + tid]  = sz;
        g_Zi[(size_t)bh*NT + bi0 + tid] = 1.0f / sz;
        g_T[(size_t)bh*NT + bi0 + tid]  = st;
    }
}

// ---------------------------------------------------------------------------
// ctx(half) = (E @ V) / Z.  fp16 mma; BK=32; 3 CTAs/SM for higher MLP.
// ---------------------------------------------------------------------------
__global__ __launch_bounds__(256, 3)
void av_mma()
{
    __shared__ __half Es[3][128][40];
    __shared__ __half Vs[3][64][40];
    __shared__ float zin[128];
    const unsigned sE = (unsigned)__cvta_generic_to_shared(&Es[0][0][0]);
    const unsigned sV = (unsigned)__cvta_generic_to_shared(&Vs[0][0][0]);

    const int tid = threadIdx.x, lane = tid & 31, warp = tid >> 5;
    const int gid = lane >> 2, tig = lane & 3;
    const int wm = warp >> 1, wn = warp & 1;
    const int bh = blockIdx.y, b = bh >> 4, h = bh & 15;
    const int bi0 = blockIdx.x * 128;

    const int lr = tid >> 1, lk16 = (tid & 1) * 16;
    const __half* Eg = g_Eh + ((size_t)bh*NT + bi0 + lr)*NT + lk16;
    const __half* Vg = g_Vh + (size_t)bh*HD*NT;
    const int vr = (tid & 127) >> 1;

    if (tid < 128) zin[tid] = g_Zi[(size_t)bh*NT + bi0 + tid];

    float4 acc[2][4];
    #pragma unroll
    for (int i = 0; i < 2; i++)
        #pragma unroll
        for (int j = 0; j < 4; j++) acc[i][j] = make_float4(0.f,0.f,0.f,0.f);

    auto issue = [&](int cc){
        int st = cc % 3, k0 = cc * 32;
        unsigned dE = sE + (unsigned)(((st*128 + lr)*40 + lk16)*2);
        cp16(dE,      Eg + k0);
        cp16(dE + 16, Eg + k0 + 8);
        if (tid < 128) {
            unsigned dV = sV + (unsigned)(((st*64 + vr)*40 + lk16)*2);
            const __half* s = Vg + (size_t)vr*NT + k0 + lk16;
            cp16(dV, s); cp16(dV + 16, s + 8);
        }
        cp_commit();
    };

    issue(0); issue(1);
    const int NCH = NT / 32;   // 64

    for (int c = 0; c < NCH; c++) {
        if (c + 1 < NCH) cp_wait1(); else cp_wait0();
        __syncthreads();
        if (c + 2 < NCH) issue(c + 2);
        const __half* Es_ = &Es[c % 3][0][0];
        const __half* Vs_ = &Vs[c % 3][0][0];

        #pragma unroll
        for (int ks = 0; ks < 2; ks++) {
            const int kb = ks * 16;
            unsigned af[2][4];
            #pragma unroll
            for (int mt = 0; mt < 2; mt++) {
                int m = wm*32 + mt*16 + gid;
                af[mt][0] = *(const unsigned*)&Es_[m*40     + kb + 2*tig];
                af[mt][1] = *(const unsigned*)&Es_[(m+8)*40 + kb + 2*tig];
                af[mt][2] = *(const unsigned*)&Es_[m*40     + kb + 2*tig + 8];
                af[mt][3] = *(const unsigned*)&Es_[(m+8)*40 + kb + 2*tig + 8];
            }
            #pragma unroll
            for (int nt = 0; nt < 4; nt++) {
                int n = wn*32 + nt*8 + gid;
                unsigned b0 = *(const unsigned*)&Vs_[n*40 + kb + 2*tig];
                unsigned b1 = *(const unsigned*)&Vs_[n*40 + kb + 2*tig + 8];
                #pragma unroll
                for (int mt = 0; mt < 2; mt++)
                    mma_f16(acc[mt][nt], af[mt][0],af[mt][1],af[mt][2],af[mt][3], b0, b1);
            }
        }
    }

    #pragma unroll
    for (int mt = 0; mt < 2; mt++) {
        int rl = wm*32 + mt*16 + gid;
        float z0 = zin[rl], z1 = zin[rl+8];
        #pragma unroll
        for (int nt = 0; nt < 4; nt++) {
            int cl = wn*32 + nt*8 + tig*2;
            float4 a = acc[mt][nt];
            size_t base = ((size_t)b*NT + bi0 + rl)*DM + h*HD + cl;
            *(__half2*)(g_ctxh + base)        = __floats2half2_rn(a.x*z0, a.y*z0);
            *(__half2*)(g_ctxh + base + 8*DM) = __floats2half2_rn(a.z*z1, a.w*z1);
        }
    }
}

// ---------------------------------------------------------------------------
__global__ __launch_bounds__(256)
void build_P_kernel()
{
    size_t idx8 = ((size_t)blockIdx.x * 256 + threadIdx.x) * 8;
    size_t b = idx8 / ((size_t)NT*NT);
    size_t rem = idx8 - b * (size_t)NT*NT;
    int i = (int)(rem >> 11);
    float s[8] = {0,0,0,0,0,0,0,0};
    #pragma unroll
    for (int h = 0; h < H; h++) {
        const uint4* src = (const uint4*)&g_Eh[(size_t)(b*H + h)*NT*NT + rem];
        uint4 raw = __ldcg(src);
        float zi = g_Zi[(size_t)(b*H + h)*NT + i];
        float2 p0 = __half22float2(*(__half2*)&raw.x);
        float2 p1 = __half22float2(*(__half2*)&raw.y);
        float2 p2 = __half22float2(*(__half2*)&raw.z);
        float2 p3 = __half22float2(*(__half2*)&raw.w);
        s[0] += p0.x*zi; s[1] += p0.y*zi; s[2] += p1.x*zi; s[3] += p1.y*zi;
        s[4] += p2.x*zi; s[5] += p2.y*zi; s[6] += p3.x*zi; s[7] += p3.y*zi;
    }
    float o[8];
    #pragma unroll
    for (int k = 0; k < 8; k++)
        o[k] = expf(logf(s[k] * (1.0f/16.0f) + EPSF) * 10.0f);
    *(float4*)&g_P[idx8]     = make_float4(o[0],o[1],o[2],o[3]);
    *(float4*)&g_P[idx8 + 4] = make_float4(o[4],o[5],o[6],o[7]);
}

// ---------------------------------------------------------------------------
__device__ __forceinline__ void grid_sync(unsigned &gen)
{
    __syncthreads();
    if (threadIdx.x == 0) {
        gen++;
        __threadfence();
        unsigned old = atomicAdd(&g_barcount, 1);
        if (old == NB_SINK - 1) {
            atomicExch(&g_barcount, 0);
            atomicExch(&g_bargen, gen);
        } else {
            while (*(volatile unsigned*)&g_bargen < gen) __nanosleep(64);
        }
    }
    __syncthreads();
}

__global__ __launch_bounds__(256)
void sinkhorn_persist(const int* __restrict__ perm, float* __restrict__ outp)
{
    __shared__ float sv[NT];
    __shared__ float su[16];
    __shared__ float red[256];
    const int tid = threadIdx.x, bk = blockIdx.x;
    const int lane = tid & 31, w = tid >> 5;
    unsigned gen = *(volatile unsigned*)&g_bargen;

    const int row0 = bk * 16;
    const int bb = row0 >> 11;
    const int blkb = bk & 127;
    const int jbase = blkb * 16;
    float* cp = g_colpart + ((size_t)bb*128 + blkb)*NT;

    if (tid < 16) {
        su[tid] = 1.0f;
        __stcg(&g_v[bb*NT + jbase + tid], 1.0f);
    }
    grid_sync(gen);

    for (int it = 0; it < 10; it++) {
        for (int j = tid; j < NT; j += 256) sv[j] = __ldcg(&g_v[bb*NT + j]);
        __syncthreads();
        #pragma unroll
        for (int rr = 0; rr < 2; rr++) {
            int rl = w*2 + rr;
            const float* Pr = g_P + (size_t)(row0 + rl)*NT;
            float s = 0.f;
            #pragma unroll 8
            for (int j = lane; j < NT; j += 32) s += Pr[j] * sv[j];
            #pragma unroll
            for (int o = 16; o > 0; o >>= 1) s += __shfl_xor_sync(0xffffffffu, s, o);
            if (lane == 0) { float u = su[rl]; su[rl] = u / (u * s + EPSF); }
        }
        __syncthreads();
        float pa[8] = {0,0,0,0,0,0,0,0};
        #pragma unroll
        for (int i = 0; i < 16; i++) {
            float ui = su[i];
            const float* Pr = g_P + (size_t)(row0 + i)*NT;
            #pragma unroll
            for (int k = 0; k < 8; k++) pa[k] += ui * Pr[tid + k*256];
        }
        #pragma unroll
        for (int k = 0; k < 8; k++) cp[tid + k*256] = pa[k];
        grid_sync(gen);
        {
            int c = tid & 15, grp = tid >> 4;
            const float* base = g_colpart + (size_t)bb*128*NT + jbase + c;
            float s = 0.f;
            #pragma unroll
            for (int kk = 0; kk < 8; kk++)
                s += __ldcg(&base[(size_t)(grp*8 + kk)*NT]);
            red[tid] = s; __syncthreads();
            if (tid < 128) red[tid] += red[tid+128];
            __syncthreads();
            if (tid < 64)  red[tid] += red[tid+64];
            __syncthreads();
            if (tid < 32)  red[tid] += red[tid+32];
            __syncthreads();
            if (tid < 16) {
                float tot = red[tid] + red[tid+16];
                int jj = bb*NT + jbase + tid;
                float v = __ldcg(&g_v[jj]);
                __stcg(&g_v[jj], v / (v * tot + EPSF));
            }
        }
        grid_sync(gen);
    }

    for (int j = tid; j < NT; j += 256) sv[j] = __ldcg(&g_v[bb*NT + j]);
    __syncthreads();
    #pragma unroll
    for (int rr = 0; rr < 2; rr++) {
        int r = row0 + w*2 + rr;
        const float* Pr = g_P + (size_t)r * NT;
        float best = -INFINITY; int bj = NT;
        for (int j = lane; j < NT; j += 32) {
            float val = Pr[j] * sv[j];
            if (val > best) { best = val; bj = j; }
        }
        #pragma unroll
        for (int o = 16; o > 0; o >>= 1) {
            float ob = __shfl_xor_sync(0xffffffffu, best, o);
            int   oj = __shfl_xor_sync(0xffffffffu, bj, o);
            if (ob > best || (ob == best && oj < bj)) { best = ob; bj = oj; }
        }
        if (lane == 0) outp[r] = (float)perm[bb*NT + bj];
    }
}

// ---------------------------------------------------------------------------
__global__ __launch_bounds__(256)
void cert_kernel(const float* __restrict__ cert, const float* __restrict__ ctemp,
                 float* __restrict__ out)
{
    const int idx = blockIdx.x * 256 + threadIdx.x;
    const int b = idx >> 11, i = idx & 2047;
    float s = 0.f;
    #pragma unroll
    for (int h = 0; h < H; h++) {
        size_t o = (size_t)(b*H + h)*NT + i;
        float Z = g_Z[o];
        s += logf(Z) - g_T[o] / Z;
    }
    float ent = s * (1.0f / 16.0f);
    float z = ctemp[0] * (logf(2048.0f) - ent);
    out[idx] = fmaxf(cert[idx], 1.0f / (1.0f + expf(-z)));
}

extern "C" void kernel_launch(void* const* d_in, const int* in_sizes, int n_in,
                              void* d_out, int out_size)
{
    const float* x     = (const float*)d_in[0];
    const float* cert  = (const float*)d_in[1];
    const int*   perm  = (const int*)  d_in[2];
    const float* Wq    = (const float*)d_in[3];
    const float* bq    = (const float*)d_in[4];
    const float* Wk    = (const float*)d_in[5];
    const float* bk    = (const float*)d_in[6];
    const float* Wv    = (const float*)d_in[7];
    const float* bvv   = (const float*)d_in[8];
    const float* Wo    = (const float*)d_in[9];
    const float* bo    = (const float*)d_in[10];
    const float* pbs   = (const float*)d_in[11];
    const float* ctemp = (const float*)d_in[12];
    float* out = (float*)d_out;

    __half *pxh, *pWqkv, *pWoh, *pCtx;
    cudaGetSymbolAddress((void**)&pxh,   g_xh);
    cudaGetSymbolAddress((void**)&pWqkv, g_Wqkvh);
    cudaGetSymbolAddress((void**)&pWoh,  g_Woh);
    cudaGetSymbolAddress((void**)&pCtx,  g_ctxh);

    const int SMEM_H = 2*3*128*40*2;                 // 61440 B
    const int SMEM_S = 1024 + 128*72*2 + 3*128*40*2; // 50176 B
    cudaFuncSetAttribute(gemm_h, cudaFuncAttributeMaxDynamicSharedMemorySize, SMEM_H);
    cudaFuncSetAttribute(scores_exp_mma, cudaFuncAttributeMaxDynamicSharedMemorySize, SMEM_S);

    const int M = B * NT;                  // 4096

    static cudaStream_t s2 = nullptr;
    static cudaEvent_t evFork = nullptr, evJoin = nullptr;
    if (s2 == nullptr) {
        cudaStreamCreateWithFlags(&s2, cudaStreamNonBlocking);
        cudaEventCreateWithFlags(&evFork, cudaEventDisableTiming);
        cudaEventCreateWithFlags(&evJoin, cudaEventDisableTiming);
    }

    cvt_all<<<8192, 256>>>(x, Wq, Wk, Wv, Wo);
    concat_bias<<<12, 256>>>(bq, bk, bvv);

    dim3 gQKV(3*DM/128, M/128);
    gemm_h<<<gQKV, 256, SMEM_H>>>(pxh, pWqkv, nullptr, nullptr, 3*DM, DM, 3);

    dim3 gS(NT/128, B*H);
    scores_exp_mma<<<gS, 256, SMEM_S>>>(pbs, perm);

    // fork: branch B (cert, build_P -> sinkhorn) on s2
    cudaEventRecord(evFork, 0);
    cudaStreamWaitEvent(s2, evFork, 0);
    cert_kernel<<<(B*NT)/256, 256, 0, s2>>>(cert, ctemp, out + (size_t)M*DM);
    build_P_kernel<<<4096, 256, 0, s2>>>();
    sinkhorn_persist<<<NB_SINK, 256, 0, s2>>>(perm, out + (size_t)M*DM + B*NT);
    cudaEventRecord(evJoin, s2);

    // branch A (av -> out projection) on main stream
    av_mma<<<gS, 256>>>();
    dim3 gO(DM/128, M/128);
    gemm_h<<<gO, 256, SMEM_H>>>(pCtx, pWoh, bo, out, DM, DM, 0);

    cudaStreamWaitEvent(0, evJoin, 0);
}